// round 9
// baseline (speedup 1.0000x reference)
#include <cuda_runtime.h>
#include <cstdint>

#define DIMS 128
#define TILE 64
#define SROW 132          // smem row stride (floats): conflict-free frag access
#define NTHREADS 256
#define NMAX 100096       // capacity of node scratch (>= 100000 spec size)

// smem layout in floats (node/edge kernels)
#define SA0 0
#define SA1 (TILE * SROW)
#define SW1 (2 * TILE * SROW)
#define SW2 (SW1 + DIMS * SROW)
#define SMEM_FLOATS (SW2 + DIMS * SROW)   // 384*132 floats = 202752 B

#define PRE_SMEM_FLOATS (2 * DIMS * SROW) // precompute kernel: 135168 B

__device__ int g_idx_is64;
// Scratch (static __device__ arrays -- the sanctioned scratch mechanism)
__device__ float g_S2[(size_t)NMAX * DIMS];   // (x @ (Wagg*Wsrc)^T)
__device__ float g_R2[(size_t)NMAX * DIMS];   // (x @ (Wagg*Wrx)^T)
__device__ float g_Wce[DIMS * DIMS];          // Wagg * Wedge
__device__ float g_Wcs[DIMS * DIMS];          // Wagg * Wsrc
__device__ float g_Wcr[DIMS * DIMS];          // Wagg * Wrx

// ---------------------------------------------------------------------------
// helpers
// ---------------------------------------------------------------------------
__device__ __forceinline__ uint32_t smem_u32(const void* p) {
    uint32_t a;
    asm("{ .reg .u64 t; cvta.to.shared.u64 t, %1; cvt.u32.u64 %0, t; }"
        : "=r"(a) : "l"(p));
    return a;
}

__device__ __forceinline__ float f2tf_rna(float f) {
    uint32_t o;
    asm("cvt.rna.tf32.f32 %0, %1;" : "=r"(o) : "f"(f));
    return __uint_as_float(o);
}

__device__ __forceinline__ void cp16(uint32_t dst, const float* src) {
    asm volatile("cp.async.cg.shared.global [%0], [%1], 16;"
                 :: "r"(dst), "l"(src));
}
#define CP_COMMIT() asm volatile("cp.async.commit_group;" ::: "memory")
#define CP_WAIT1()  asm volatile("cp.async.wait_group 1;" ::: "memory")

__device__ __forceinline__ void mma8(float c[4], const uint32_t a[4],
                                     const uint32_t b[2]) {
    asm volatile(
        "mma.sync.aligned.m16n8k8.row.col.f32.tf32.tf32.f32 "
        "{%0,%1,%2,%3}, {%4,%5,%6,%7}, {%8,%9}, {%0,%1,%2,%3};"
        : "+f"(c[0]), "+f"(c[1]), "+f"(c[2]), "+f"(c[3])
        : "r"(a[0]), "r"(a[1]), "r"(a[2]), "r"(a[3]), "r"(b[0]), "r"(b[1]));
}

// Weight [128,128] fp32 -> smem (RNA-rounded to tf32), once per CTA.
__device__ __forceinline__ void load_w(const float* __restrict__ w, float* s) {
    int tid = threadIdx.x;
    #pragma unroll 4
    for (int idx = tid; idx < DIMS * 32; idx += NTHREADS) {
        int row = idx >> 5;
        int kc  = idx & 31;
        float4 v = *(const float4*)(w + row * DIMS + kc * 4);
        v.x = f2tf_rna(v.x); v.y = f2tf_rna(v.y);
        v.z = f2tf_rna(v.z); v.w = f2tf_rna(v.w);
        *(float4*)(s + row * SROW + kc * 4) = v;
    }
}

// Async prefetch of a 64-row tile (raw fp32; rounded later in registers).
__device__ __forceinline__ void prefetch_tile(const float* __restrict__ g,
                                              size_t row0, int nrows,
                                              uint32_t sbuf_bytes) {
    int tid = threadIdx.x;
    #pragma unroll
    for (int it = 0; it < (TILE * 32) / NTHREADS; it++) {
        int idx = tid + it * NTHREADS;
        int row = idx >> 5;
        int kc  = idx & 31;
        if (row < nrows)
            cp16(sbuf_bytes + (uint32_t)(row * SROW + kc * 4) * 4,
                 g + (row0 + row) * DIMS + kc * 4);
    }
}

// ---------------------------------------------------------------------------
// Dual 64x128x128 GEMM sharing A fragments: c1 += A*B1^T, c2 += A*B2^T.
// 8 warps as 2(row) x 4(col), warp tile 32x32 each.
// Accum c[i][j][4]: row = wr*32 + i*16 + qr + 8h, col = wc*32 + j*8 + qc*2(+1).
// ---------------------------------------------------------------------------
template <bool CVT>
__device__ __forceinline__ void gemm_dual(const float* __restrict__ As,
                                          const float* __restrict__ B1s,
                                          const float* __restrict__ B2s,
                                          float c1[2][4][4], float c2[2][4][4]) {
    int wid = threadIdx.x >> 5, lane = threadIdx.x & 31;
    int wr = wid & 1, wc = wid >> 1;
    int qr = lane >> 2, qc = lane & 3;
    const float* Ab  = As  + (wr * 32 + qr) * SROW + qc;
    const float* B1b = B1s + (wc * 32 + qr) * SROW + qc;
    const float* B2b = B2s + (wc * 32 + qr) * SROW + qc;

    #pragma unroll 2
    for (int k = 0; k < DIMS; k += 8) {
        uint32_t a[2][4], b1[4][2], b2[4][2];
        #pragma unroll
        for (int i = 0; i < 2; i++) {
            const float* p = Ab + i * 16 * SROW + k;
            float a0 = p[0], a1 = p[8 * SROW], a2 = p[4], a3 = p[8 * SROW + 4];
            if (CVT) {
                a0 = f2tf_rna(a0); a1 = f2tf_rna(a1);
                a2 = f2tf_rna(a2); a3 = f2tf_rna(a3);
            }
            a[i][0] = __float_as_uint(a0); a[i][1] = __float_as_uint(a1);
            a[i][2] = __float_as_uint(a2); a[i][3] = __float_as_uint(a3);
        }
        #pragma unroll
        for (int j = 0; j < 4; j++) {
            const float* p = B1b + j * 8 * SROW + k;
            b1[j][0] = __float_as_uint(p[0]);
            b1[j][1] = __float_as_uint(p[4]);
            const float* q = B2b + j * 8 * SROW + k;
            b2[j][0] = __float_as_uint(q[0]);
            b2[j][1] = __float_as_uint(q[4]);
        }
        #pragma unroll
        for (int i = 0; i < 2; i++)
            #pragma unroll
            for (int j = 0; j < 4; j++) {
                mma8(c1[i][j], a[i], b1[j]);
                mma8(c2[i][j], a[i], b2[j]);
            }
    }
}

// Single GEMM variant (fallback path).
template <bool CVT>
__device__ __forceinline__ void gemm_single(const float* __restrict__ As,
                                            const float* __restrict__ Bs,
                                            float c[2][4][4]) {
    int wid = threadIdx.x >> 5, lane = threadIdx.x & 31;
    int wr = wid & 1, wc = wid >> 1;
    int qr = lane >> 2, qc = lane & 3;
    const float* Ab = As + (wr * 32 + qr) * SROW + qc;
    const float* Bb = Bs + (wc * 32 + qr) * SROW + qc;

    #pragma unroll 4
    for (int k = 0; k < DIMS; k += 8) {
        uint32_t a[2][4], b[4][2];
        #pragma unroll
        for (int i = 0; i < 2; i++) {
            const float* p = Ab + i * 16 * SROW + k;
            float a0 = p[0], a1 = p[8 * SROW], a2 = p[4], a3 = p[8 * SROW + 4];
            if (CVT) {
                a0 = f2tf_rna(a0); a1 = f2tf_rna(a1);
                a2 = f2tf_rna(a2); a3 = f2tf_rna(a3);
            }
            a[i][0] = __float_as_uint(a0); a[i][1] = __float_as_uint(a1);
            a[i][2] = __float_as_uint(a2); a[i][3] = __float_as_uint(a3);
        }
        #pragma unroll
        for (int j = 0; j < 4; j++) {
            const float* p = Bb + j * 8 * SROW + k;
            b[j][0] = __float_as_uint(p[0]);
            b[j][1] = __float_as_uint(p[4]);
        }
        #pragma unroll
        for (int i = 0; i < 2; i++)
            #pragma unroll
            for (int j = 0; j < 4; j++) mma8(c[i][j], a[i], b[j]);
    }
}

__device__ __forceinline__ void acc_zero2(float c1[2][4][4], float c2[2][4][4]) {
    #pragma unroll
    for (int i = 0; i < 2; i++)
        #pragma unroll
        for (int j = 0; j < 4; j++)
            #pragma unroll
            for (int q = 0; q < 4; q++) { c1[i][j][q] = 0.f; c2[i][j][q] = 0.f; }
}

// ---------------------------------------------------------------------------
// Precompute kernel: 3 CTAs compute (Wagg*Wedge, Wagg*Wsrc, Wagg*Wrx) in fp32.
// Block 0 thread 0 also detects edge_index dtype.
// ---------------------------------------------------------------------------
extern __shared__ float smem[];

__global__ void __launch_bounds__(NTHREADS, 1)
precompute_kernel(const float* __restrict__ Wagg, const float* __restrict__ Wedge,
                  const float* __restrict__ Wsrc, const float* __restrict__ Wrx,
                  const void* __restrict__ eidx, int n_nodes) {
    if (blockIdx.x == 0 && threadIdx.x == 0) {
        const long long* p = (const long long*)eidx;
        int ok = 1;
        for (int i = 0; i < 32; i++) {
            long long v = p[i];
            if (v < 0 || v >= (long long)n_nodes) ok = 0;
        }
        g_idx_is64 = ok;
    }

    float* SWA = smem;
    float* SX  = smem + DIMS * SROW;
    const float* X = (blockIdx.x == 0) ? Wedge : (blockIdx.x == 1) ? Wsrc : Wrx;
    float* OUT = (blockIdx.x == 0) ? g_Wce : (blockIdx.x == 1) ? g_Wcs : g_Wcr;

    int tid = threadIdx.x;
    #pragma unroll 4
    for (int idx = tid; idx < DIMS * 32; idx += NTHREADS) {
        int row = idx >> 5, kc = idx & 31;
        *(float4*)(SWA + row * SROW + kc * 4) = *(const float4*)(Wagg + row * DIMS + kc * 4);
        *(float4*)(SX  + row * SROW + kc * 4) = *(const float4*)(X    + row * DIMS + kc * 4);
    }
    __syncthreads();

    int r = tid >> 1;
    int c0 = (tid & 1) * 64;
    float acc[64];
    #pragma unroll
    for (int j = 0; j < 64; j++) acc[j] = 0.f;
    for (int k = 0; k < DIMS; k++) {
        float a = SWA[r * SROW + k];
        #pragma unroll
        for (int j4 = 0; j4 < 16; j4++) {
            float4 xv = *(const float4*)(SX + k * SROW + c0 + j4 * 4);
            acc[j4 * 4 + 0] = fmaf(a, xv.x, acc[j4 * 4 + 0]);
            acc[j4 * 4 + 1] = fmaf(a, xv.y, acc[j4 * 4 + 1]);
            acc[j4 * 4 + 2] = fmaf(a, xv.z, acc[j4 * 4 + 2]);
            acc[j4 * 4 + 3] = fmaf(a, xv.w, acc[j4 * 4 + 3]);
        }
    }
    #pragma unroll
    for (int j4 = 0; j4 < 16; j4++)
        *(float4*)(OUT + r * DIMS + c0 + j4 * 4) =
            make_float4(acc[j4 * 4], acc[j4 * 4 + 1], acc[j4 * 4 + 2], acc[j4 * 4 + 3]);
}

// ---------------------------------------------------------------------------
// Shared node-kernel body: o1 = x@W1^T, o2 = x@W2^T  (dual GEMM per tile).
// ---------------------------------------------------------------------------
__device__ __forceinline__ void node_body(const float* __restrict__ x,
                                          const float* __restrict__ W1,
                                          const float* __restrict__ W2,
                                          float* __restrict__ o1,
                                          float* __restrict__ o2,
                                          int n_nodes, int tiles_per_cta, int ntiles) {
    uint32_t sb = smem_u32(smem);
    int t0 = blockIdx.x * tiles_per_cta;
    if (t0 >= ntiles) return;
    int t1 = min(t0 + tiles_per_cta, ntiles);

    load_w(W1, smem + SW1);
    load_w(W2, smem + SW2);
    prefetch_tile(x, (size_t)t0 * TILE, min(TILE, n_nodes - t0 * TILE), sb + SA0 * 4);
    CP_COMMIT();

    int wid = threadIdx.x >> 5, lane = threadIdx.x & 31;
    int wr = wid & 1, wc = wid >> 1;
    int qr = lane >> 2, qc = lane & 3;

    for (int t = t0; t < t1; t++) {
        int buf = (t - t0) & 1;
        float* A = smem + (buf ? SA1 : SA0);
        if (t + 1 < t1)
            prefetch_tile(x, (size_t)(t + 1) * TILE,
                          min(TILE, n_nodes - (t + 1) * TILE),
                          sb + (buf ? SA0 : SA1) * 4);
        CP_COMMIT();
        CP_WAIT1();
        __syncthreads();

        int nvalid = min(TILE, n_nodes - t * TILE);
        float c1[2][4][4], c2[2][4][4];
        acc_zero2(c1, c2);
        gemm_dual<true>(A, smem + SW1, smem + SW2, c1, c2);

        #pragma unroll
        for (int i = 0; i < 2; i++)
            #pragma unroll
            for (int h = 0; h < 2; h++) {
                int r = wr * 32 + i * 16 + qr + 8 * h;
                if (r < nvalid) {
                    size_t rowoff = ((size_t)t * TILE + r) * DIMS + wc * 32 + qc * 2;
                    #pragma unroll
                    for (int j = 0; j < 4; j++) {
                        *(float2*)(o1 + rowoff + j * 8) =
                            make_float2(c1[i][j][2 * h], c1[i][j][2 * h + 1]);
                        *(float2*)(o2 + rowoff + j * 8) =
                            make_float2(c2[i][j][2 * h], c2[i][j][2 * h + 1]);
                    }
                }
            }
        __syncthreads();   // all warps done with A before next prefetch reuses it
    }
}

__global__ void __launch_bounds__(NTHREADS, 1)
node_kernel(const float* __restrict__ x, const float* __restrict__ W1,
            const float* __restrict__ W2, float* __restrict__ o1,
            float* __restrict__ o2, int n_nodes, int tiles_per_cta, int ntiles) {
    node_body(x, W1, W2, o1, o2, n_nodes, tiles_per_cta, ntiles);
}

// node2: writes the S2/R2 scratch tables using the precomputed combo weights.
__global__ void __launch_bounds__(NTHREADS, 1)
node2_kernel(const float* __restrict__ x, int n_nodes, int tiles_per_cta, int ntiles) {
    node_body(x, g_Wcs, g_Wcr, g_S2, g_R2, n_nodes, tiles_per_cta, ntiles);
}

// ---------------------------------------------------------------------------
// Edge kernel (fast path): per tile, ONE shared-A dual GEMM:
//   c1 = eattr @ Wedge^T          -> out_edge
//   c2 = eattr @ (Wagg*Wedge)^T   -> + g_S2[u] + g_R2[v] -> out_upd
// ---------------------------------------------------------------------------
__global__ void __launch_bounds__(NTHREADS, 1)
edge_kernel(const float* __restrict__ eattr, const void* __restrict__ eidx,
            const float* __restrict__ Wedge,
            float* __restrict__ out_edge, float* __restrict__ out_upd,
            int n_edges, int tiles_per_cta, int ntiles) {
    uint32_t sb = smem_u32(smem);
    int t0 = blockIdx.x * tiles_per_cta;
    if (t0 >= ntiles) return;
    int t1 = min(t0 + tiles_per_cta, ntiles);

    load_w(Wedge, smem + SW1);
    load_w(g_Wce, smem + SW2);
    prefetch_tile(eattr, (size_t)t0 * TILE, min(TILE, n_edges - t0 * TILE),
                  sb + SA0 * 4);
    CP_COMMIT();

    int wid = threadIdx.x >> 5, lane = threadIdx.x & 31;
    int wr = wid & 1, wc = wid >> 1;
    int qr = lane >> 2, qc = lane & 3;
    int is64 = g_idx_is64;
    const long long* p64 = (const long long*)eidx;
    const int*       p32 = (const int*)eidx;

    for (int t = t0; t < t1; t++) {
        int buf = (t - t0) & 1;
        float* A = smem + (buf ? SA1 : SA0);
        if (t + 1 < t1)
            prefetch_tile(eattr, (size_t)(t + 1) * TILE,
                          min(TILE, n_edges - (t + 1) * TILE),
                          sb + (buf ? SA0 : SA1) * 4);
        CP_COMMIT();
        CP_WAIT1();
        __syncthreads();

        int nvalid = min(TILE, n_edges - t * TILE);
        float c1[2][4][4], c2[2][4][4];
        acc_zero2(c1, c2);
        gemm_dual<true>(A, smem + SW1, smem + SW2, c1, c2);

        // Epilogue: write edge_embed; add gathered S2[u]+R2[v] to c2 -> upd.
        #pragma unroll
        for (int i = 0; i < 2; i++)
            #pragma unroll
            for (int h = 0; h < 2; h++) {
                int r = wr * 32 + i * 16 + qr + 8 * h;
                if (r < nvalid) {
                    size_t e = (size_t)t * TILE + r;
                    long long u, v;
                    if (is64) { u = p64[e]; v = p64[(size_t)n_edges + e]; }
                    else      { u = p32[e]; v = p32[(size_t)n_edges + e]; }
                    int colb = wc * 32 + qc * 2;
                    float* ge = out_edge + e * DIMS + colb;
                    float* go = out_upd  + e * DIMS + colb;
                    const float* s2 = g_S2 + (size_t)u * DIMS + colb;
                    const float* r2 = g_R2 + (size_t)v * DIMS + colb;
                    #pragma unroll
                    for (int j = 0; j < 4; j++) {
                        *(float2*)(ge + j * 8) =
                            make_float2(c1[i][j][2 * h], c1[i][j][2 * h + 1]);
                        float2 s = *(const float2*)(s2 + j * 8);
                        float2 rr = *(const float2*)(r2 + j * 8);
                        *(float2*)(go + j * 8) =
                            make_float2(c2[i][j][2 * h] + s.x + rr.x,
                                        c2[i][j][2 * h + 1] + s.y + rr.y);
                    }
                }
            }
        __syncthreads();   // protect A before next prefetch reuses it
    }
}

// ---------------------------------------------------------------------------
// Fallback fused edge kernel (R5, proven): used only if N > NMAX.
// ---------------------------------------------------------------------------
__global__ void __launch_bounds__(NTHREADS, 1)
edge_fused_kernel(const float* __restrict__ eattr, const void* __restrict__ eidx,
                  const float* __restrict__ Wedge, const float* __restrict__ Wagg,
                  const float* __restrict__ src_embed, const float* __restrict__ rx_embed,
                  float* __restrict__ out_edge, float* __restrict__ out_upd,
                  int n_edges, int tiles_per_cta, int ntiles) {
    uint32_t sb = smem_u32(smem);
    int t0 = blockIdx.x * tiles_per_cta;
    if (t0 >= ntiles) return;
    int t1 = min(t0 + tiles_per_cta, ntiles);

    load_w(Wedge, smem + SW1);
    load_w(Wagg,  smem + SW2);
    prefetch_tile(eattr, (size_t)t0 * TILE, min(TILE, n_edges - t0 * TILE),
                  sb + SA0 * 4);
    CP_COMMIT();

    int wid = threadIdx.x >> 5, lane = threadIdx.x & 31;
    int wr = wid & 1, wc = wid >> 1;
    int qr = lane >> 2, qc = lane & 3;
    int is64 = g_idx_is64;
    const long long* p64 = (const long long*)eidx;
    const int*       p32 = (const int*)eidx;

    for (int t = t0; t < t1; t++) {
        int buf = (t - t0) & 1;
        float* A = smem + (buf ? SA1 : SA0);
        if (t + 1 < t1)
            prefetch_tile(eattr, (size_t)(t + 1) * TILE,
                          min(TILE, n_edges - (t + 1) * TILE),
                          sb + (buf ? SA0 : SA1) * 4);
        CP_COMMIT();
        CP_WAIT1();
        __syncthreads();

        int nvalid = min(TILE, n_edges - t * TILE);
        float c[2][4][4];
        #pragma unroll
        for (int i = 0; i < 2; i++)
            #pragma unroll
            for (int j = 0; j < 4; j++)
                #pragma unroll
                for (int q = 0; q < 4; q++) c[i][j][q] = 0.f;
        gemm_single<true>(A, smem + SW1, c);
        __syncthreads();

        #pragma unroll
        for (int i = 0; i < 2; i++)
            #pragma unroll
            for (int h = 0; h < 2; h++) {
                int r = wr * 32 + i * 16 + qr + 8 * h;
                if (r < nvalid) {
                    size_t e = (size_t)t * TILE + r;
                    long long u, v;
                    if (is64) { u = p64[e]; v = p64[(size_t)n_edges + e]; }
                    else      { u = p32[e]; v = p32[(size_t)n_edges + e]; }
                    int colb = wc * 32 + qc * 2;
                    float* ge = out_edge + e * DIMS + colb;
                    const float* su = src_embed + (size_t)u * DIMS + colb;
                    const float* rv = rx_embed  + (size_t)v * DIMS + colb;
                    float* sa = A + r * SROW + colb;
                    #pragma unroll
                    for (int j = 0; j < 4; j++) {
                        float2 a = make_float2(c[i][j][2 * h], c[i][j][2 * h + 1]);
                        *(float2*)(ge + j * 8) = a;
                        float2 s2 = *(const float2*)(su + j * 8);
                        float2 r2 = *(const float2*)(rv + j * 8);
                        a.x = f2tf_rna(a.x + s2.x + r2.x);
                        a.y = f2tf_rna(a.y + s2.y + r2.y);
                        *(float2*)(sa + j * 8) = a;
                    }
                }
            }
        __syncthreads();

        #pragma unroll
        for (int i = 0; i < 2; i++)
            #pragma unroll
            for (int j = 0; j < 4; j++)
                #pragma unroll
                for (int q = 0; q < 4; q++) c[i][j][q] = 0.f;
        gemm_single<false>(A, smem + SW2, c);
        #pragma unroll
        for (int i = 0; i < 2; i++)
            #pragma unroll
            for (int h = 0; h < 2; h++) {
                int r = wr * 32 + i * 16 + qr + 8 * h;
                if (r < nvalid) {
                    float* go = out_upd + ((size_t)t * TILE + r) * DIMS
                              + wc * 32 + qc * 2;
                    #pragma unroll
                    for (int j = 0; j < 4; j++)
                        *(float2*)(go + j * 8) =
                            make_float2(c[i][j][2 * h], c[i][j][2 * h + 1]);
                }
            }
        __syncthreads();
    }
}

// ---------------------------------------------------------------------------
// Launch: inputs x, edge_index, edge_attr, W_src, W_edge, W_rx, W_agg
// Output: concat(src_embed[N,D], edge_embed[E,D], rx_embed[N,D], updated[E,D])
// ---------------------------------------------------------------------------
extern "C" void kernel_launch(void* const* d_in, const int* in_sizes, int n_in,
                              void* d_out, int out_size) {
    const float* x     = (const float*)d_in[0];
    const void*  eidx  = d_in[1];
    const float* eattr = (const float*)d_in[2];
    const float* Wsrc  = (const float*)d_in[3];
    const float* Wedge = (const float*)d_in[4];
    const float* Wrx   = (const float*)d_in[5];
    const float* Wagg  = (const float*)d_in[6];

    int N = in_sizes[0] / DIMS;
    int E = in_sizes[2] / DIMS;

    float* out      = (float*)d_out;
    float* out_src  = out;
    float* out_edge = out_src + (size_t)N * DIMS;
    float* out_rx   = out_edge + (size_t)E * DIMS;
    float* out_upd  = out_rx + (size_t)N * DIMS;

    int ntiles_n = (N + TILE - 1) / TILE;
    int ntiles_e = (E + TILE - 1) / TILE;
    int tpc_n = (ntiles_n + 147) / 148;
    int grid_n = (ntiles_n + tpc_n - 1) / tpc_n;
    int tpc_e = (ntiles_e + 4 * 148 - 1) / (4 * 148);
    int grid_e = (ntiles_e + tpc_e - 1) / tpc_e;

    size_t smem_bytes = (size_t)SMEM_FLOATS * sizeof(float);      // 202752
    size_t pre_bytes  = (size_t)PRE_SMEM_FLOATS * sizeof(float);  // 135168
    cudaFuncSetAttribute(precompute_kernel, cudaFuncAttributeMaxDynamicSharedMemorySize,
                         (int)pre_bytes);
    cudaFuncSetAttribute(node_kernel, cudaFuncAttributeMaxDynamicSharedMemorySize,
                         (int)smem_bytes);
    cudaFuncSetAttribute(node2_kernel, cudaFuncAttributeMaxDynamicSharedMemorySize,
                         (int)smem_bytes);
    cudaFuncSetAttribute(edge_kernel, cudaFuncAttributeMaxDynamicSharedMemorySize,
                         (int)smem_bytes);
    cudaFuncSetAttribute(edge_fused_kernel, cudaFuncAttributeMaxDynamicSharedMemorySize,
                         (int)smem_bytes);

    precompute_kernel<<<3, NTHREADS, pre_bytes>>>(Wagg, Wedge, Wsrc, Wrx, eidx, N);

    if (N <= NMAX) {
        node2_kernel<<<grid_n, NTHREADS, smem_bytes>>>(x, N, tpc_n, ntiles_n);
        edge_kernel<<<grid_e, NTHREADS, smem_bytes>>>(
            eattr, eidx, Wedge, out_edge, out_upd, E, tpc_e, ntiles_e);
        node_kernel<<<grid_n, NTHREADS, smem_bytes>>>(
            x, Wsrc, Wrx, out_src, out_rx, N, tpc_n, ntiles_n);
    } else {
        node_kernel<<<grid_n, NTHREADS, smem_bytes>>>(
            x, Wsrc, Wrx, out_src, out_rx, N, tpc_n, ntiles_n);
        edge_fused_kernel<<<grid_e, NTHREADS, smem_bytes>>>(
            eattr, eidx, Wedge, Wagg, out_src, out_rx, out_edge, out_upd,
            E, tpc_e, ntiles_e);
    }
}

// round 10
// speedup vs baseline: 1.1597x; 1.1597x over previous
#include <cuda_runtime.h>
#include <cstdint>

#define DIMS 128
#define TILE 64
#define SROW 132          // smem row stride (floats): conflict-free frag access
#define NTHREADS 512      // 16 warps: 4 per SMSP (R5 had 8 total -> latency-bound)

// smem layout in floats
#define SA0 0
#define SA1 (TILE * SROW)
#define SW1 (2 * TILE * SROW)
#define SW2 (SW1 + DIMS * SROW)
#define SMEM_FLOATS (SW2 + DIMS * SROW)   // 384*132 = 50688 floats = 202752 B

__device__ int g_idx_is64;

// ---------------------------------------------------------------------------
// helpers
// ---------------------------------------------------------------------------
__device__ __forceinline__ uint32_t smem_u32(const void* p) {
    uint32_t a;
    asm("{ .reg .u64 t; cvta.to.shared.u64 t, %1; cvt.u32.u64 %0, t; }"
        : "=r"(a) : "l"(p));
    return a;
}

__device__ __forceinline__ float f2tf_rna(float f) {
    uint32_t o;
    asm("cvt.rna.tf32.f32 %0, %1;" : "=r"(o) : "f"(f));
    return __uint_as_float(o);
}

__device__ __forceinline__ void cp16(uint32_t dst, const float* src) {
    asm volatile("cp.async.cg.shared.global [%0], [%1], 16;"
                 :: "r"(dst), "l"(src));
}
#define CP_COMMIT() asm volatile("cp.async.commit_group;" ::: "memory")
#define CP_WAIT1()  asm volatile("cp.async.wait_group 1;" ::: "memory")

__device__ __forceinline__ void mma8(float c[4], const uint32_t a[4],
                                     const uint32_t b[2]) {
    asm volatile(
        "mma.sync.aligned.m16n8k8.row.col.f32.tf32.tf32.f32 "
        "{%0,%1,%2,%3}, {%4,%5,%6,%7}, {%8,%9}, {%0,%1,%2,%3};"
        : "+f"(c[0]), "+f"(c[1]), "+f"(c[2]), "+f"(c[3])
        : "r"(a[0]), "r"(a[1]), "r"(a[2]), "r"(a[3]), "r"(b[0]), "r"(b[1]));
}

// Weight [128,128] fp32 -> smem (RNA-rounded to tf32), once per CTA.
__device__ __forceinline__ void load_w(const float* __restrict__ w, float* s) {
    int tid = threadIdx.x;
    #pragma unroll
    for (int it = 0; it < (DIMS * 32) / NTHREADS; it++) {
        int idx = tid + it * NTHREADS;
        int row = idx >> 5;
        int kc  = idx & 31;
        float4 v = *(const float4*)(w + row * DIMS + kc * 4);
        v.x = f2tf_rna(v.x); v.y = f2tf_rna(v.y);
        v.z = f2tf_rna(v.z); v.w = f2tf_rna(v.w);
        *(float4*)(s + row * SROW + kc * 4) = v;
    }
}

// Async prefetch of a 64-row tile (raw fp32; rounded later in registers).
__device__ __forceinline__ void prefetch_tile(const float* __restrict__ g,
                                              size_t row0, int nrows,
                                              uint32_t sbuf_bytes) {
    int tid = threadIdx.x;
    #pragma unroll
    for (int it = 0; it < (TILE * 32) / NTHREADS; it++) {
        int idx = tid + it * NTHREADS;
        int row = idx >> 5;
        int kc  = idx & 31;
        if (row < nrows)
            cp16(sbuf_bytes + (uint32_t)(row * SROW + kc * 4) * 4,
                 g + (row0 + row) * DIMS + kc * 4);
    }
}

// ---------------------------------------------------------------------------
// 64x128x128 warp-tiled tf32 GEMM, 16 warps as 2(row) x 8(col).
// Warp tile 32(M) x 16(N). Accum c[i][j][4] (i: m16 tile, j: n8 tile):
//   row = wr*32 + i*16 + qr + 8h,  col = wc*16 + j*8 + qc*2 (+1)
// Bank check: addr%32 = (4*row + qc + k)%32 -> 8 qr x 4 qc all distinct.
// CVT: RNA-round A fragments (raw fp32 tiles arrive via cp.async).
// ---------------------------------------------------------------------------
template <bool CVT>
__device__ __forceinline__ void gemm64(const float* __restrict__ As,
                                       const float* __restrict__ Bs,
                                       float c[2][2][4]) {
    int wid = threadIdx.x >> 5, lane = threadIdx.x & 31;
    int wr = wid & 1, wc = wid >> 1;
    int qr = lane >> 2, qc = lane & 3;
    const float* Ab = As + (wr * 32 + qr) * SROW + qc;
    const float* Bb = Bs + (wc * 16 + qr) * SROW + qc;

    #pragma unroll 4
    for (int k = 0; k < DIMS; k += 8) {
        uint32_t a[2][4], b[2][2];
        #pragma unroll
        for (int i = 0; i < 2; i++) {
            const float* p = Ab + i * 16 * SROW + k;
            float a0 = p[0], a1 = p[8 * SROW], a2 = p[4], a3 = p[8 * SROW + 4];
            if (CVT) {
                a0 = f2tf_rna(a0); a1 = f2tf_rna(a1);
                a2 = f2tf_rna(a2); a3 = f2tf_rna(a3);
            }
            a[i][0] = __float_as_uint(a0); a[i][1] = __float_as_uint(a1);
            a[i][2] = __float_as_uint(a2); a[i][3] = __float_as_uint(a3);
        }
        #pragma unroll
        for (int j = 0; j < 2; j++) {
            const float* p = Bb + j * 8 * SROW + k;
            b[j][0] = __float_as_uint(p[0]);
            b[j][1] = __float_as_uint(p[4]);
        }
        #pragma unroll
        for (int i = 0; i < 2; i++)
            #pragma unroll
            for (int j = 0; j < 2; j++) mma8(c[i][j], a[i], b[j]);
    }
}

__device__ __forceinline__ void acc_zero(float c[2][2][4]) {
    #pragma unroll
    for (int i = 0; i < 2; i++)
        #pragma unroll
        for (int j = 0; j < 2; j++)
            #pragma unroll
            for (int q = 0; q < 4; q++) c[i][j][q] = 0.f;
}

// ---------------------------------------------------------------------------
// Node kernel: persistent over tiles; src = x@Wsrc^T, rx = x@Wrx^T.
// Block 0 thread 0 also detects edge_index dtype (node runs before edge).
// ---------------------------------------------------------------------------
extern __shared__ float smem[];

__global__ void __launch_bounds__(NTHREADS, 1)
node_kernel(const float* __restrict__ x, const float* __restrict__ Wsrc,
            const float* __restrict__ Wrx, const void* __restrict__ eidx,
            float* __restrict__ out_src, float* __restrict__ out_rx,
            int n_nodes, int tiles_per_cta, int ntiles) {
    if (blockIdx.x == 0 && threadIdx.x == 0) {
        const long long* p = (const long long*)eidx;
        int ok = 1;
        for (int i = 0; i < 32; i++) {
            long long v = p[i];
            if (v < 0 || v >= (long long)n_nodes) ok = 0;
        }
        g_idx_is64 = ok;
    }

    uint32_t sb = smem_u32(smem);
    int t0 = blockIdx.x * tiles_per_cta;
    if (t0 >= ntiles) return;
    int t1 = min(t0 + tiles_per_cta, ntiles);

    load_w(Wsrc, smem + SW1);
    load_w(Wrx,  smem + SW2);
    prefetch_tile(x, (size_t)t0 * TILE, min(TILE, n_nodes - t0 * TILE), sb + SA0 * 4);
    CP_COMMIT();

    int wid = threadIdx.x >> 5, lane = threadIdx.x & 31;
    int wr = wid & 1, wc = wid >> 1;
    int qr = lane >> 2, qc = lane & 3;

    for (int t = t0; t < t1; t++) {
        int buf = (t - t0) & 1;
        float* A = smem + (buf ? SA1 : SA0);
        if (t + 1 < t1)
            prefetch_tile(x, (size_t)(t + 1) * TILE,
                          min(TILE, n_nodes - (t + 1) * TILE),
                          sb + (buf ? SA0 : SA1) * 4);
        CP_COMMIT();
        CP_WAIT1();
        __syncthreads();

        int nvalid = min(TILE, n_nodes - t * TILE);
        float c[2][2][4];

        #pragma unroll
        for (int g = 0; g < 2; g++) {
            float* outp = g ? out_rx : out_src;
            acc_zero(c);
            if (g == 0) gemm64<true>(A, smem + SW1, c);
            else        gemm64<true>(A, smem + SW2, c);
            #pragma unroll
            for (int i = 0; i < 2; i++)
                #pragma unroll
                for (int h = 0; h < 2; h++) {
                    int r = wr * 32 + i * 16 + qr + 8 * h;
                    if (r < nvalid) {
                        float* gp = outp + ((size_t)t * TILE + r) * DIMS
                                  + wc * 16 + qc * 2;
                        #pragma unroll
                        for (int j = 0; j < 2; j++)
                            *(float2*)(gp + j * 8) =
                                make_float2(c[i][j][2 * h], c[i][j][2 * h + 1]);
                    }
                }
        }
        __syncthreads();   // all warps done with A before next prefetch reuses it
    }
}

// ---------------------------------------------------------------------------
// Edge kernel: persistent over tiles.
//   edge_embed = edge_attr @ Wedge^T  (written out)
//   agg = edge_embed + src[u] + rx[v] (RNA, rebuilt in A buffer)
//   updated = agg @ Wagg^T            (written out)
// ---------------------------------------------------------------------------
__global__ void __launch_bounds__(NTHREADS, 1)
edge_kernel(const float* __restrict__ eattr, const void* __restrict__ eidx,
            const float* __restrict__ Wedge, const float* __restrict__ Wagg,
            const float* __restrict__ src_embed, const float* __restrict__ rx_embed,
            float* __restrict__ out_edge, float* __restrict__ out_upd,
            int n_edges, int tiles_per_cta, int ntiles) {
    uint32_t sb = smem_u32(smem);
    int t0 = blockIdx.x * tiles_per_cta;
    if (t0 >= ntiles) return;
    int t1 = min(t0 + tiles_per_cta, ntiles);

    load_w(Wedge, smem + SW1);
    load_w(Wagg,  smem + SW2);
    prefetch_tile(eattr, (size_t)t0 * TILE, min(TILE, n_edges - t0 * TILE),
                  sb + SA0 * 4);
    CP_COMMIT();

    int wid = threadIdx.x >> 5, lane = threadIdx.x & 31;
    int wr = wid & 1, wc = wid >> 1;
    int qr = lane >> 2, qc = lane & 3;
    int is64 = g_idx_is64;
    const long long* p64 = (const long long*)eidx;
    const int*       p32 = (const int*)eidx;

    for (int t = t0; t < t1; t++) {
        int buf = (t - t0) & 1;
        float* A = smem + (buf ? SA1 : SA0);
        if (t + 1 < t1)
            prefetch_tile(eattr, (size_t)(t + 1) * TILE,
                          min(TILE, n_edges - (t + 1) * TILE),
                          sb + (buf ? SA0 : SA1) * 4);
        CP_COMMIT();
        CP_WAIT1();
        __syncthreads();

        int nvalid = min(TILE, n_edges - t * TILE);
        float c[2][2][4];
        acc_zero(c);
        gemm64<true>(A, smem + SW1, c);       // edge_embed in regs
        __syncthreads();                       // all reads of A done

        // Epilogue 1: write edge_embed, gather src[u]+rx[v], agg (RNA) -> A.
        #pragma unroll
        for (int i = 0; i < 2; i++)
            #pragma unroll
            for (int h = 0; h < 2; h++) {
                int r = wr * 32 + i * 16 + qr + 8 * h;
                if (r < nvalid) {
                    size_t e = (size_t)t * TILE + r;
                    long long u, v;
                    if (is64) { u = p64[e]; v = p64[(size_t)n_edges + e]; }
                    else      { u = p32[e]; v = p32[(size_t)n_edges + e]; }
                    int colb = wc * 16 + qc * 2;
                    float* ge = out_edge + e * DIMS + colb;
                    const float* su = src_embed + (size_t)u * DIMS + colb;
                    const float* rv = rx_embed  + (size_t)v * DIMS + colb;
                    float* sa = A + r * SROW + colb;
                    #pragma unroll
                    for (int j = 0; j < 2; j++) {
                        float2 a = make_float2(c[i][j][2 * h], c[i][j][2 * h + 1]);
                        *(float2*)(ge + j * 8) = a;
                        float2 s2 = *(const float2*)(su + j * 8);
                        float2 r2 = *(const float2*)(rv + j * 8);
                        a.x = f2tf_rna(a.x + s2.x + r2.x);
                        a.y = f2tf_rna(a.y + s2.y + r2.y);
                        *(float2*)(sa + j * 8) = a;
                    }
                }
            }
        __syncthreads();

        acc_zero(c);
        gemm64<false>(A, smem + SW2, c);      // updated_edge
        #pragma unroll
        for (int i = 0; i < 2; i++)
            #pragma unroll
            for (int h = 0; h < 2; h++) {
                int r = wr * 32 + i * 16 + qr + 8 * h;
                if (r < nvalid) {
                    float* go = out_upd + ((size_t)t * TILE + r) * DIMS
                              + wc * 16 + qc * 2;
                    #pragma unroll
                    for (int j = 0; j < 2; j++)
                        *(float2*)(go + j * 8) =
                            make_float2(c[i][j][2 * h], c[i][j][2 * h + 1]);
                }
            }
        __syncthreads();   // protect A before next iteration's prefetch reuses it
    }
}

// ---------------------------------------------------------------------------
// Launch: inputs x, edge_index, edge_attr, W_src, W_edge, W_rx, W_agg
// Output: concat(src_embed[N,D], edge_embed[E,D], rx_embed[N,D], updated[E,D])
// ---------------------------------------------------------------------------
extern "C" void kernel_launch(void* const* d_in, const int* in_sizes, int n_in,
                              void* d_out, int out_size) {
    const float* x     = (const float*)d_in[0];
    const void*  eidx  = d_in[1];
    const float* eattr = (const float*)d_in[2];
    const float* Wsrc  = (const float*)d_in[3];
    const float* Wedge = (const float*)d_in[4];
    const float* Wrx   = (const float*)d_in[5];
    const float* Wagg  = (const float*)d_in[6];

    int N = in_sizes[0] / DIMS;
    int E = in_sizes[2] / DIMS;

    float* out      = (float*)d_out;
    float* out_src  = out;
    float* out_edge = out_src + (size_t)N * DIMS;
    float* out_rx   = out_edge + (size_t)E * DIMS;
    float* out_upd  = out_rx + (size_t)N * DIMS;

    int ntiles_n = (N + TILE - 1) / TILE;
    int ntiles_e = (E + TILE - 1) / TILE;
    int tpc_n = (ntiles_n + 147) / 148;          // ~1 wave of CTAs
    int grid_n = (ntiles_n + tpc_n - 1) / tpc_n;
    int tpc_e = (ntiles_e + 4 * 148 - 1) / (4 * 148);  // ~4 waves
    int grid_e = (ntiles_e + tpc_e - 1) / tpc_e;

    size_t smem_bytes = (size_t)SMEM_FLOATS * sizeof(float);  // 202752 B
    cudaFuncSetAttribute(node_kernel, cudaFuncAttributeMaxDynamicSharedMemorySize,
                         (int)smem_bytes);
    cudaFuncSetAttribute(edge_kernel, cudaFuncAttributeMaxDynamicSharedMemorySize,
                         (int)smem_bytes);

    node_kernel<<<grid_n, NTHREADS, smem_bytes>>>(
        x, Wsrc, Wrx, eidx, out_src, out_rx, N, tpc_n, ntiles_n);
    edge_kernel<<<grid_e, NTHREADS, smem_bytes>>>(
        eattr, eidx, Wedge, Wagg, out_src, out_rx, out_edge, out_upd,
        E, tpc_e, ntiles_e);
}

// round 15
// speedup vs baseline: 1.2885x; 1.1110x over previous
#include <cuda_runtime.h>
#include <cstdint>

#define DIMS 128
#define TILE 64
#define SROW 132          // smem row stride (floats): conflict-free frag access
#define NTHREADS 256      // R5-proven config (512 regressed: L1 contention)

// smem layout in floats
#define SA0 0
#define SA1 (TILE * SROW)
#define SW1 (2 * TILE * SROW)
#define SW2 (SW1 + DIMS * SROW)
#define SMEM_FLOATS (SW2 + DIMS * SROW)   // 384*132 = 50688 floats = 202752 B

__device__ int g_idx_is64;

// ---------------------------------------------------------------------------
// helpers
// ---------------------------------------------------------------------------
__device__ __forceinline__ uint32_t smem_u32(const void* p) {
    uint32_t a;
    asm("{ .reg .u64 t; cvta.to.shared.u64 t, %1; cvt.u32.u64 %0, t; }"
        : "=r"(a) : "l"(p));
    return a;
}

__device__ __forceinline__ float f2tf_rna(float f) {
    uint32_t o;
    asm("cvt.rna.tf32.f32 %0, %1;" : "=r"(o) : "f"(f));
    return __uint_as_float(o);
}

__device__ __forceinline__ void cp16(uint32_t dst, const float* src) {
    asm volatile("cp.async.cg.shared.global [%0], [%1], 16;"
                 :: "r"(dst), "l"(src));
}
#define CP_COMMIT() asm volatile("cp.async.commit_group;" ::: "memory")
#define CP_WAIT1()  asm volatile("cp.async.wait_group 1;" ::: "memory")

// Early-issued gather load: asm volatile pins the issue point BEFORE the GEMM
// so the L2/DRAM latency overlaps with tensor work instead of stalling the
// epilogue.
__device__ __forceinline__ float2 ldg2_pin(const float* p) {
    float2 v;
    asm volatile("ld.global.nc.v2.f32 {%0,%1}, [%2];"
                 : "=f"(v.x), "=f"(v.y) : "l"(p));
    return v;
}

__device__ __forceinline__ void mma8(float c[4], const uint32_t a[4],
                                     const uint32_t b[2]) {
    asm volatile(
        "mma.sync.aligned.m16n8k8.row.col.f32.tf32.tf32.f32 "
        "{%0,%1,%2,%3}, {%4,%5,%6,%7}, {%8,%9}, {%0,%1,%2,%3};"
        : "+f"(c[0]), "+f"(c[1]), "+f"(c[2]), "+f"(c[3])
        : "r"(a[0]), "r"(a[1]), "r"(a[2]), "r"(a[3]), "r"(b[0]), "r"(b[1]));
}

// Weight [128,128] fp32 -> smem (RNA-rounded to tf32), once per CTA.
__device__ __forceinline__ void load_w(const float* __restrict__ w, float* s) {
    int tid = threadIdx.x;
    #pragma unroll
    for (int it = 0; it < (DIMS * 32) / NTHREADS; it++) {
        int idx = tid + it * NTHREADS;
        int row = idx >> 5;
        int kc  = idx & 31;
        float4 v = *(const float4*)(w + row * DIMS + kc * 4);
        v.x = f2tf_rna(v.x); v.y = f2tf_rna(v.y);
        v.z = f2tf_rna(v.z); v.w = f2tf_rna(v.w);
        *(float4*)(s + row * SROW + kc * 4) = v;
    }
}

// Async prefetch of a 64-row tile (raw fp32; rounded later in registers).
__device__ __forceinline__ void prefetch_tile(const float* __restrict__ g,
                                              size_t row0, int nrows,
                                              uint32_t sbuf_bytes) {
    int tid = threadIdx.x;
    #pragma unroll
    for (int it = 0; it < (TILE * 32) / NTHREADS; it++) {
        int idx = tid + it * NTHREADS;
        int row = idx >> 5;
        int kc  = idx & 31;
        if (row < nrows)
            cp16(sbuf_bytes + (uint32_t)(row * SROW + kc * 4) * 4,
                 g + (row0 + row) * DIMS + kc * 4);
    }
}

// ---------------------------------------------------------------------------
// 64x128x128 warp-tiled tf32 GEMM: 8 warps as 2(row) x 4(col), warp tile
// 32x32 (R5-proven). Accum c[i][j][4]:
//   row = wr*32 + i*16 + qr + 8h,  col = wc*32 + j*8 + qc*2 (+1)
// CVT: RNA-round A fragments (raw fp32 tiles arrive via cp.async).
// ---------------------------------------------------------------------------
template <bool CVT>
__device__ __forceinline__ void gemm64(const float* __restrict__ As,
                                       const float* __restrict__ Bs,
                                       float c[2][4][4]) {
    int wid = threadIdx.x >> 5, lane = threadIdx.x & 31;
    int wr = wid & 1, wc = wid >> 1;
    int qr = lane >> 2, qc = lane & 3;
    const float* Ab = As + (wr * 32 + qr) * SROW + qc;
    const float* Bb = Bs + (wc * 32 + qr) * SROW + qc;

    #pragma unroll 4
    for (int k = 0; k < DIMS; k += 8) {
        uint32_t a[2][4], b[4][2];
        #pragma unroll
        for (int i = 0; i < 2; i++) {
            const float* p = Ab + i * 16 * SROW + k;
            float a0 = p[0], a1 = p[8 * SROW], a2 = p[4], a3 = p[8 * SROW + 4];
            if (CVT) {
                a0 = f2tf_rna(a0); a1 = f2tf_rna(a1);
                a2 = f2tf_rna(a2); a3 = f2tf_rna(a3);
            }
            a[i][0] = __float_as_uint(a0); a[i][1] = __float_as_uint(a1);
            a[i][2] = __float_as_uint(a2); a[i][3] = __float_as_uint(a3);
        }
        #pragma unroll
        for (int j = 0; j < 4; j++) {
            const float* p = Bb + j * 8 * SROW + k;
            b[j][0] = __float_as_uint(p[0]);
            b[j][1] = __float_as_uint(p[4]);
        }
        #pragma unroll
        for (int i = 0; i < 2; i++)
            #pragma unroll
            for (int j = 0; j < 4; j++) mma8(c[i][j], a[i], b[j]);
    }
}

__device__ __forceinline__ void acc_zero(float c[2][4][4]) {
    #pragma unroll
    for (int i = 0; i < 2; i++)
        #pragma unroll
        for (int j = 0; j < 4; j++)
            #pragma unroll
            for (int q = 0; q < 4; q++) c[i][j][q] = 0.f;
}

// ---------------------------------------------------------------------------
// Node kernel: persistent over tiles; src = x@Wsrc^T, rx = x@Wrx^T.
// Block 0 thread 0 also detects edge_index dtype (node runs before edge).
// ---------------------------------------------------------------------------
extern __shared__ float smem[];

__global__ void __launch_bounds__(NTHREADS, 1)
node_kernel(const float* __restrict__ x, const float* __restrict__ Wsrc,
            const float* __restrict__ Wrx, const void* __restrict__ eidx,
            float* __restrict__ out_src, float* __restrict__ out_rx,
            int n_nodes, int tiles_per_cta, int ntiles) {
    if (blockIdx.x == 0 && threadIdx.x == 0) {
        const long long* p = (const long long*)eidx;
        int ok = 1;
        for (int i = 0; i < 32; i++) {
            long long v = p[i];
            if (v < 0 || v >= (long long)n_nodes) ok = 0;
        }
        g_idx_is64 = ok;
    }

    uint32_t sb = smem_u32(smem);
    int t0 = blockIdx.x * tiles_per_cta;
    if (t0 >= ntiles) return;
    int t1 = min(t0 + tiles_per_cta, ntiles);

    load_w(Wsrc, smem + SW1);
    load_w(Wrx,  smem + SW2);
    prefetch_tile(x, (size_t)t0 * TILE, min(TILE, n_nodes - t0 * TILE), sb + SA0 * 4);
    CP_COMMIT();

    int wid = threadIdx.x >> 5, lane = threadIdx.x & 31;
    int wr = wid & 1, wc = wid >> 1;
    int qr = lane >> 2, qc = lane & 3;

    for (int t = t0; t < t1; t++) {
        int buf = (t - t0) & 1;
        float* A = smem + (buf ? SA1 : SA0);
        if (t + 1 < t1)
            prefetch_tile(x, (size_t)(t + 1) * TILE,
                          min(TILE, n_nodes - (t + 1) * TILE),
                          sb + (buf ? SA0 : SA1) * 4);
        CP_COMMIT();
        CP_WAIT1();
        __syncthreads();

        int nvalid = min(TILE, n_nodes - t * TILE);
        float c[2][4][4];

        #pragma unroll
        for (int g = 0; g < 2; g++) {
            float* outp = g ? out_rx : out_src;
            acc_zero(c);
            if (g == 0) gemm64<true>(A, smem + SW1, c);
            else        gemm64<true>(A, smem + SW2, c);
            #pragma unroll
            for (int i = 0; i < 2; i++)
                #pragma unroll
                for (int h = 0; h < 2; h++) {
                    int r = wr * 32 + i * 16 + qr + 8 * h;
                    if (r < nvalid) {
                        float* gp = outp + ((size_t)t * TILE + r) * DIMS
                                  + wc * 32 + qc * 2;
                        #pragma unroll
                        for (int j = 0; j < 4; j++)
                            *(float2*)(gp + j * 8) =
                                make_float2(c[i][j][2 * h], c[i][j][2 * h + 1]);
                    }
                }
        }
        __syncthreads();   // all warps done with A before next prefetch reuses it
    }
}

// ---------------------------------------------------------------------------
// Edge kernel: persistent over tiles.
//   edge_embed = edge_attr @ Wedge^T  (written out)
//   agg = edge_embed + src[u] + rx[v] (RNA, rebuilt in A buffer)
//   updated = agg @ Wagg^T            (written out)
// Gather loads for src[u]/rx[v] are issued BEFORE GEMM1 (pinned with asm) so
// their L2/DRAM latency hides behind the tensor work.
// ---------------------------------------------------------------------------
__global__ void __launch_bounds__(NTHREADS, 1)
edge_kernel(const float* __restrict__ eattr, const void* __restrict__ eidx,
            const float* __restrict__ Wedge, const float* __restrict__ Wagg,
            const float* __restrict__ src_embed, const float* __restrict__ rx_embed,
            float* __restrict__ out_edge, float* __restrict__ out_upd,
            int n_edges, int tiles_per_cta, int ntiles) {
    uint32_t sb = smem_u32(smem);
    int t0 = blockIdx.x * tiles_per_cta;
    if (t0 >= ntiles) return;
    int t1 = min(t0 + tiles_per_cta, ntiles);

    load_w(Wedge, smem + SW1);
    load_w(Wagg,  smem + SW2);
    prefetch_tile(eattr, (size_t)t0 * TILE, min(TILE, n_edges - t0 * TILE),
                  sb + SA0 * 4);
    CP_COMMIT();

    int wid = threadIdx.x >> 5, lane = threadIdx.x & 31;
    int wr = wid & 1, wc = wid >> 1;
    int qr = lane >> 2, qc = lane & 3;
    int is64 = g_idx_is64;
    const long long* p64 = (const long long*)eidx;
    const int*       p32 = (const int*)eidx;

    for (int t = t0; t < t1; t++) {
        int buf = (t - t0) & 1;
        float* A = smem + (buf ? SA1 : SA0);
        if (t + 1 < t1)
            prefetch_tile(eattr, (size_t)(t + 1) * TILE,
                          min(TILE, n_edges - (t + 1) * TILE),
                          sb + (buf ? SA0 : SA1) * 4);
        CP_COMMIT();
        CP_WAIT1();
        __syncthreads();

        int nvalid = min(TILE, n_edges - t * TILE);

        // -- Pre-gather: issue all src[u]/rx[v] loads before GEMM1 ----------
        // Thread covers rows r(i,h) = wr*32+i*16+qr+8h, cols wc*32+qc*2+8j.
        float2 su[4][4], rv[4][4];   // [row(i*2+h)][j]
        #pragma unroll
        for (int i = 0; i < 2; i++)
            #pragma unroll
            for (int h = 0; h < 2; h++) {
                int r = wr * 32 + i * 16 + qr + 8 * h;
                int ri = i * 2 + h;
                if (r < nvalid) {
                    size_t e = (size_t)t * TILE + r;
                    long long u, v;
                    if (is64) { u = p64[e]; v = p64[(size_t)n_edges + e]; }
                    else      { u = p32[e]; v = p32[(size_t)n_edges + e]; }
                    const float* sup = src_embed + (size_t)u * DIMS + wc * 32 + qc * 2;
                    const float* rvp = rx_embed  + (size_t)v * DIMS + wc * 32 + qc * 2;
                    #pragma unroll
                    for (int j = 0; j < 4; j++) {
                        su[ri][j] = ldg2_pin(sup + j * 8);
                        rv[ri][j] = ldg2_pin(rvp + j * 8);
                    }
                } else {
                    #pragma unroll
                    for (int j = 0; j < 4; j++) {
                        su[ri][j] = make_float2(0.f, 0.f);
                        rv[ri][j] = make_float2(0.f, 0.f);
                    }
                }
            }

        // -- GEMM1 (covers the gather latency) ------------------------------
        float c[2][4][4];
        acc_zero(c);
        gemm64<true>(A, smem + SW1, c);       // edge_embed in regs
        __syncthreads();                       // all reads of A done

        // -- Epilogue 1: pure stores/adds (gathers already in registers) ----
        #pragma unroll
        for (int i = 0; i < 2; i++)
            #pragma unroll
            for (int h = 0; h < 2; h++) {
                int r = wr * 32 + i * 16 + qr + 8 * h;
                int ri = i * 2 + h;
                if (r < nvalid) {
                    size_t e = (size_t)t * TILE + r;
                    int colb = wc * 32 + qc * 2;
                    float* ge = out_edge + e * DIMS + colb;
                    float* sa = A + r * SROW + colb;
                    #pragma unroll
                    for (int j = 0; j < 4; j++) {
                        float2 a = make_float2(c[i][j][2 * h], c[i][j][2 * h + 1]);
                        *(float2*)(ge + j * 8) = a;          // edge_embed out
                        a.x = f2tf_rna(a.x + su[ri][j].x + rv[ri][j].x);
                        a.y = f2tf_rna(a.y + su[ri][j].y + rv[ri][j].y);
                        *(float2*)(sa + j * 8) = a;          // agg (tf32) to smem
                    }
                }
            }
        __syncthreads();

        // -- GEMM2: updated_edge = agg @ Wagg^T -----------------------------
        acc_zero(c);
        gemm64<false>(A, smem + SW2, c);
        #pragma unroll
        for (int i = 0; i < 2; i++)
            #pragma unroll
            for (int h = 0; h < 2; h++) {
                int r = wr * 32 + i * 16 + qr + 8 * h;
                if (r < nvalid) {
                    float* go = out_upd + ((size_t)t * TILE + r) * DIMS
                              + wc * 32 + qc * 2;
                    #pragma unroll
                    for (int j = 0; j < 4; j++)
                        *(float2*)(go + j * 8) =
                            make_float2(c[i][j][2 * h], c[i][j][2 * h + 1]);
                }
            }
        __syncthreads();   // protect A before next iteration's prefetch reuses it
    }
}

// ---------------------------------------------------------------------------
// Launch: inputs x, edge_index, edge_attr, W_src, W_edge, W_rx, W_agg
// Output: concat(src_embed[N,D], edge_embed[E,D], rx_embed[N,D], updated[E,D])
// ---------------------------------------------------------------------------
extern "C" void kernel_launch(void* const* d_in, const int* in_sizes, int n_in,
                              void* d_out, int out_size) {
    const float* x     = (const float*)d_in[0];
    const void*  eidx  = d_in[1];
    const float* eattr = (const float*)d_in[2];
    const float* Wsrc  = (const float*)d_in[3];
    const float* Wedge = (const float*)d_in[4];
    const float* Wrx   = (const float*)d_in[5];
    const float* Wagg  = (const float*)d_in[6];

    int N = in_sizes[0] / DIMS;
    int E = in_sizes[2] / DIMS;

    float* out      = (float*)d_out;
    float* out_src  = out;
    float* out_edge = out_src + (size_t)N * DIMS;
    float* out_rx   = out_edge + (size_t)E * DIMS;
    float* out_upd  = out_rx + (size_t)N * DIMS;

    int ntiles_n = (N + TILE - 1) / TILE;
    int ntiles_e = (E + TILE - 1) / TILE;
    int tpc_n = (ntiles_n + 147) / 148;          // ~1 wave of CTAs
    int grid_n = (ntiles_n + tpc_n - 1) / tpc_n;
    int tpc_e = (ntiles_e + 4 * 148 - 1) / (4 * 148);  // ~4 waves
    int grid_e = (ntiles_e + tpc_e - 1) / tpc_e;

    size_t smem_bytes = (size_t)SMEM_FLOATS * sizeof(float);  // 202752 B
    cudaFuncSetAttribute(node_kernel, cudaFuncAttributeMaxDynamicSharedMemorySize,
                         (int)smem_bytes);
    cudaFuncSetAttribute(edge_kernel, cudaFuncAttributeMaxDynamicSharedMemorySize,
                         (int)smem_bytes);

    node_kernel<<<grid_n, NTHREADS, smem_bytes>>>(
        x, Wsrc, Wrx, eidx, out_src, out_rx, N, tpc_n, ntiles_n);
    edge_kernel<<<grid_e, NTHREADS, smem_bytes>>>(
        eattr, eidx, Wedge, Wagg, out_src, out_rx, out_edge, out_upd,
        E, tpc_e, ntiles_e);
}

// round 16
// speedup vs baseline: 1.3466x; 1.0450x over previous
#include <cuda_runtime.h>
#include <cstdint>

#define DIMS 128
#define TILE 64
#define SROW 132          // smem row stride (floats): conflict-free frag access
#define NTHREADS 256

// smem layout in floats
#define SA0 0
#define SA1 (TILE * SROW)
#define SW1 (2 * TILE * SROW)
#define SW2 (SW1 + DIMS * SROW)
#define SMEM_FLOATS (SW2 + DIMS * SROW)   // 384*132 = 50688 floats = 202752 B

__device__ int g_idx_is64;

// ---------------------------------------------------------------------------
// helpers
// ---------------------------------------------------------------------------
__device__ __forceinline__ uint32_t smem_u32(const void* p) {
    uint32_t a;
    asm("{ .reg .u64 t; cvta.to.shared.u64 t, %1; cvt.u32.u64 %0, t; }"
        : "=r"(a) : "l"(p));
    return a;
}

__device__ __forceinline__ float f2tf_rna(float f) {
    uint32_t o;
    asm("cvt.rna.tf32.f32 %0, %1;" : "=r"(o) : "f"(f));
    return __uint_as_float(o);
}

__device__ __forceinline__ void cp16(uint32_t dst, const float* src) {
    asm volatile("cp.async.cg.shared.global [%0], [%1], 16;"
                 :: "r"(dst), "l"(src));
}
#define CP_COMMIT() asm volatile("cp.async.commit_group;" ::: "memory")
#define CP_WAIT0()  asm volatile("cp.async.wait_group 0;" ::: "memory")

// Early-issued gather load (pinned so latency hides behind the GEMM phase).
__device__ __forceinline__ float2 ldg2_pin(const float* p) {
    float2 v;
    asm volatile("ld.global.nc.v2.f32 {%0,%1}, [%2];"
                 : "=f"(v.x), "=f"(v.y) : "l"(p));
    return v;
}

__device__ __forceinline__ void mma8(float c[4], const uint32_t a[4],
                                     const uint32_t b[2]) {
    asm volatile(
        "mma.sync.aligned.m16n8k8.row.col.f32.tf32.tf32.f32 "
        "{%0,%1,%2,%3}, {%4,%5,%6,%7}, {%8,%9}, {%0,%1,%2,%3};"
        : "+f"(c[0]), "+f"(c[1]), "+f"(c[2]), "+f"(c[3])
        : "r"(a[0]), "r"(a[1]), "r"(a[2]), "r"(a[3]), "r"(b[0]), "r"(b[1]));
}

// Weight [128,128] fp32 -> smem (RNA-rounded to tf32), once per CTA.
__device__ __forceinline__ void load_w(const float* __restrict__ w, float* s) {
    int tid = threadIdx.x;
    #pragma unroll
    for (int it = 0; it < (DIMS * 32) / NTHREADS; it++) {
        int idx = tid + it * NTHREADS;
        int row = idx >> 5;
        int kc  = idx & 31;
        float4 v = *(const float4*)(w + row * DIMS + kc * 4);
        v.x = f2tf_rna(v.x); v.y = f2tf_rna(v.y);
        v.z = f2tf_rna(v.z); v.w = f2tf_rna(v.w);
        *(float4*)(s + row * SROW + kc * 4) = v;
    }
}

// Async prefetch of a 64-row tile (raw fp32; rounded later in registers).
__device__ __forceinline__ void prefetch_tile(const float* __restrict__ g,
                                              size_t row0, int nrows,
                                              uint32_t sbuf_bytes) {
    int tid = threadIdx.x;
    #pragma unroll
    for (int it = 0; it < (TILE * 32) / NTHREADS; it++) {
        int idx = tid + it * NTHREADS;
        int row = idx >> 5;
        int kc  = idx & 31;
        if (row < nrows)
            cp16(sbuf_bytes + (uint32_t)(row * SROW + kc * 4) * 4,
                 g + (row0 + row) * DIMS + kc * 4);
    }
}

// ---------------------------------------------------------------------------
// 64x128x128 warp-tiled tf32 GEMM: 8 warps as 2(row) x 4(col), warp tile
// 32x32. Accum c[i][j][4]:
//   row = wr*32 + i*16 + qr + 8h,  col = wc*32 + j*8 + qc*2 (+1)
// ---------------------------------------------------------------------------
template <bool CVT>
__device__ __forceinline__ void gemm64(const float* __restrict__ As,
                                       const float* __restrict__ Bs,
                                       float c[2][4][4]) {
    int wid = threadIdx.x >> 5, lane = threadIdx.x & 31;
    int wr = wid & 1, wc = wid >> 1;
    int qr = lane >> 2, qc = lane & 3;
    const float* Ab = As + (wr * 32 + qr) * SROW + qc;
    const float* Bb = Bs + (wc * 32 + qr) * SROW + qc;

    #pragma unroll 4
    for (int k = 0; k < DIMS; k += 8) {
        uint32_t a[2][4], b[4][2];
        #pragma unroll
        for (int i = 0; i < 2; i++) {
            const float* p = Ab + i * 16 * SROW + k;
            float a0 = p[0], a1 = p[8 * SROW], a2 = p[4], a3 = p[8 * SROW + 4];
            if (CVT) {
                a0 = f2tf_rna(a0); a1 = f2tf_rna(a1);
                a2 = f2tf_rna(a2); a3 = f2tf_rna(a3);
            }
            a[i][0] = __float_as_uint(a0); a[i][1] = __float_as_uint(a1);
            a[i][2] = __float_as_uint(a2); a[i][3] = __float_as_uint(a3);
        }
        #pragma unroll
        for (int j = 0; j < 4; j++) {
            const float* p = Bb + j * 8 * SROW + k;
            b[j][0] = __float_as_uint(p[0]);
            b[j][1] = __float_as_uint(p[4]);
        }
        #pragma unroll
        for (int i = 0; i < 2; i++)
            #pragma unroll
            for (int j = 0; j < 4; j++) mma8(c[i][j], a[i], b[j]);
    }
}

// Cross-tile dual GEMM: c2 += A2@B2^T (no cvt: agg already tf32),
//                       c1 += A1@B1^T (cvt: raw eattr tile).
// 16 independent mma per k-step -> double ILP across the phase.
__device__ __forceinline__ void gemm_dual2(const float* __restrict__ A2s,
                                           const float* __restrict__ B2s,
                                           float c2[2][4][4],
                                           const float* __restrict__ A1s,
                                           const float* __restrict__ B1s,
                                           float c1[2][4][4]) {
    int wid = threadIdx.x >> 5, lane = threadIdx.x & 31;
    int wr = wid & 1, wc = wid >> 1;
    int qr = lane >> 2, qc = lane & 3;
    const float* A2b = A2s + (wr * 32 + qr) * SROW + qc;
    const float* A1b = A1s + (wr * 32 + qr) * SROW + qc;
    const float* B2b = B2s + (wc * 32 + qr) * SROW + qc;
    const float* B1b = B1s + (wc * 32 + qr) * SROW + qc;

    #pragma unroll 2
    for (int k = 0; k < DIMS; k += 8) {
        uint32_t a2[2][4], a1[2][4], b2[4][2], b1[4][2];
        #pragma unroll
        for (int i = 0; i < 2; i++) {
            const float* p = A2b + i * 16 * SROW + k;
            a2[i][0] = __float_as_uint(p[0]);
            a2[i][1] = __float_as_uint(p[8 * SROW]);
            a2[i][2] = __float_as_uint(p[4]);
            a2[i][3] = __float_as_uint(p[8 * SROW + 4]);
            const float* q = A1b + i * 16 * SROW + k;
            a1[i][0] = __float_as_uint(f2tf_rna(q[0]));
            a1[i][1] = __float_as_uint(f2tf_rna(q[8 * SROW]));
            a1[i][2] = __float_as_uint(f2tf_rna(q[4]));
            a1[i][3] = __float_as_uint(f2tf_rna(q[8 * SROW + 4]));
        }
        #pragma unroll
        for (int j = 0; j < 4; j++) {
            const float* p = B2b + j * 8 * SROW + k;
            b2[j][0] = __float_as_uint(p[0]);
            b2[j][1] = __float_as_uint(p[4]);
            const float* q = B1b + j * 8 * SROW + k;
            b1[j][0] = __float_as_uint(q[0]);
            b1[j][1] = __float_as_uint(q[4]);
        }
        #pragma unroll
        for (int i = 0; i < 2; i++)
            #pragma unroll
            for (int j = 0; j < 4; j++) {
                mma8(c2[i][j], a2[i], b2[j]);
                mma8(c1[i][j], a1[i], b1[j]);
            }
    }
}

__device__ __forceinline__ void acc_zero(float c[2][4][4]) {
    #pragma unroll
    for (int i = 0; i < 2; i++)
        #pragma unroll
        for (int j = 0; j < 4; j++)
            #pragma unroll
            for (int q = 0; q < 4; q++) c[i][j][q] = 0.f;
}

// ---------------------------------------------------------------------------
// Node kernel: persistent over tiles; src = x@Wsrc^T, rx = x@Wrx^T.
// Block 0 thread 0 also detects edge_index dtype (node launches first).
// ---------------------------------------------------------------------------
extern __shared__ float smem[];

__global__ void __launch_bounds__(NTHREADS, 1)
node_kernel(const float* __restrict__ x, const float* __restrict__ Wsrc,
            const float* __restrict__ Wrx, const void* __restrict__ eidx,
            float* __restrict__ out_src, float* __restrict__ out_rx,
            int n_nodes, int tiles_per_cta, int ntiles) {
    if (blockIdx.x == 0 && threadIdx.x == 0) {
        const long long* p = (const long long*)eidx;
        int ok = 1;
        for (int i = 0; i < 32; i++) {
            long long v = p[i];
            if (v < 0 || v >= (long long)n_nodes) ok = 0;
        }
        g_idx_is64 = ok;
    }

    uint32_t sb = smem_u32(smem);
    int t0 = blockIdx.x * tiles_per_cta;
    if (t0 >= ntiles) return;
    int t1 = min(t0 + tiles_per_cta, ntiles);

    load_w(Wsrc, smem + SW1);
    load_w(Wrx,  smem + SW2);
    prefetch_tile(x, (size_t)t0 * TILE, min(TILE, n_nodes - t0 * TILE), sb + SA0 * 4);
    CP_COMMIT();

    int wid = threadIdx.x >> 5, lane = threadIdx.x & 31;
    int wr = wid & 1, wc = wid >> 1;
    int qr = lane >> 2, qc = lane & 3;

    for (int t = t0; t < t1; t++) {
        int buf = (t - t0) & 1;
        float* A = smem + (buf ? SA1 : SA0);
        if (t + 1 < t1)
            prefetch_tile(x, (size_t)(t + 1) * TILE,
                          min(TILE, n_nodes - (t + 1) * TILE),
                          sb + (buf ? SA0 : SA1) * 4);
        CP_COMMIT();
        CP_WAIT0();
        __syncthreads();

        int nvalid = min(TILE, n_nodes - t * TILE);
        float c[2][4][4];

        #pragma unroll
        for (int g = 0; g < 2; g++) {
            float* outp = g ? out_rx : out_src;
            acc_zero(c);
            if (g == 0) gemm64<true>(A, smem + SW1, c);
            else        gemm64<true>(A, smem + SW2, c);
            #pragma unroll
            for (int i = 0; i < 2; i++)
                #pragma unroll
                for (int h = 0; h < 2; h++) {
                    int r = wr * 32 + i * 16 + qr + 8 * h;
                    if (r < nvalid) {
                        float* gp = outp + ((size_t)t * TILE + r) * DIMS
                                  + wc * 32 + qc * 2;
                        #pragma unroll
                        for (int j = 0; j < 4; j++)
                            *(float2*)(gp + j * 8) =
                                make_float2(c[i][j][2 * h], c[i][j][2 * h + 1]);
                    }
                }
        }
        __syncthreads();   // all warps done with A before next prefetch reuses it
    }
}

// ---------------------------------------------------------------------------
// Edge kernel: cross-tile software pipeline.
//   prologue: GEMM1(t0) -> edge out + agg(t0)
//   loop i:   dual[GEMM2(i) | GEMM1(i+1)] -> upd(i) out, edge(i+1) out, agg(i+1)
//   tail:     GEMM2(t1-1) -> upd out
// agg(t) lives in A-buffer[t&1] (overwrites the eattr tile in place).
// ---------------------------------------------------------------------------
struct Gath { float2 su[4][4], rv[4][4]; };

__device__ __forceinline__ void pregather(const void* eidx, int is64,
                                          int n_edges, int t, int nvalid,
                                          const float* __restrict__ src_embed,
                                          const float* __restrict__ rx_embed,
                                          Gath& g) {
    int wid = threadIdx.x >> 5, lane = threadIdx.x & 31;
    int wr = wid & 1, wc = wid >> 1;
    int qr = lane >> 2, qc = lane & 3;
    const long long* p64 = (const long long*)eidx;
    const int*       p32 = (const int*)eidx;
    #pragma unroll
    for (int i = 0; i < 2; i++)
        #pragma unroll
        for (int h = 0; h < 2; h++) {
            int r = wr * 32 + i * 16 + qr + 8 * h;
            int ri = i * 2 + h;
            if (r < nvalid) {
                size_t e = (size_t)t * TILE + r;
                long long u, v;
                if (is64) { u = p64[e]; v = p64[(size_t)n_edges + e]; }
                else      { u = p32[e]; v = p32[(size_t)n_edges + e]; }
                const float* sup = src_embed + (size_t)u * DIMS + wc * 32 + qc * 2;
                const float* rvp = rx_embed  + (size_t)v * DIMS + wc * 32 + qc * 2;
                #pragma unroll
                for (int j = 0; j < 4; j++) {
                    g.su[ri][j] = ldg2_pin(sup + j * 8);
                    g.rv[ri][j] = ldg2_pin(rvp + j * 8);
                }
            } else {
                #pragma unroll
                for (int j = 0; j < 4; j++) {
                    g.su[ri][j] = make_float2(0.f, 0.f);
                    g.rv[ri][j] = make_float2(0.f, 0.f);
                }
            }
        }
}

// Epilogue for GEMM1 of tile t: write edge_embed, build agg (tf32) into A.
__device__ __forceinline__ void epi1(float c1[2][4][4], const Gath& g,
                                     float* __restrict__ A,
                                     float* __restrict__ out_edge,
                                     int t, int nvalid) {
    int wid = threadIdx.x >> 5, lane = threadIdx.x & 31;
    int wr = wid & 1, wc = wid >> 1;
    int qr = lane >> 2, qc = lane & 3;
    #pragma unroll
    for (int i = 0; i < 2; i++)
        #pragma unroll
        for (int h = 0; h < 2; h++) {
            int r = wr * 32 + i * 16 + qr + 8 * h;
            int ri = i * 2 + h;
            if (r < nvalid) {
                size_t e = (size_t)t * TILE + r;
                int colb = wc * 32 + qc * 2;
                float* ge = out_edge + e * DIMS + colb;
                float* sa = A + r * SROW + colb;
                #pragma unroll
                for (int j = 0; j < 4; j++) {
                    float2 a = make_float2(c1[i][j][2 * h], c1[i][j][2 * h + 1]);
                    *(float2*)(ge + j * 8) = a;
                    a.x = f2tf_rna(a.x + g.su[ri][j].x + g.rv[ri][j].x);
                    a.y = f2tf_rna(a.y + g.su[ri][j].y + g.rv[ri][j].y);
                    *(float2*)(sa + j * 8) = a;
                }
            }
        }
}

// Epilogue for GEMM2 of tile t: write updated_edge.
__device__ __forceinline__ void epi2(float c2[2][4][4],
                                     float* __restrict__ out_upd,
                                     int t, int nvalid) {
    int wid = threadIdx.x >> 5, lane = threadIdx.x & 31;
    int wr = wid & 1, wc = wid >> 1;
    int qr = lane >> 2, qc = lane & 3;
    #pragma unroll
    for (int i = 0; i < 2; i++)
        #pragma unroll
        for (int h = 0; h < 2; h++) {
            int r = wr * 32 + i * 16 + qr + 8 * h;
            if (r < nvalid) {
                float* go = out_upd + ((size_t)t * TILE + r) * DIMS
                          + wc * 32 + qc * 2;
                #pragma unroll
                for (int j = 0; j < 4; j++)
                    *(float2*)(go + j * 8) =
                        make_float2(c2[i][j][2 * h], c2[i][j][2 * h + 1]);
            }
        }
}

__global__ void __launch_bounds__(NTHREADS)
edge_kernel(const float* __restrict__ eattr, const void* __restrict__ eidx,
            const float* __restrict__ Wedge, const float* __restrict__ Wagg,
            const float* __restrict__ src_embed, const float* __restrict__ rx_embed,
            float* __restrict__ out_edge, float* __restrict__ out_upd,
            int n_edges, int tiles_per_cta, int ntiles) {
    uint32_t sb = smem_u32(smem);
    int t0 = blockIdx.x * tiles_per_cta;
    if (t0 >= ntiles) return;
    int t1 = min(t0 + tiles_per_cta, ntiles);

    load_w(Wedge, smem + SW1);
    load_w(Wagg,  smem + SW2);
    prefetch_tile(eattr, (size_t)t0 * TILE, min(TILE, n_edges - t0 * TILE),
                  sb + ((t0 & 1) ? SA1 : SA0) * 4);
    CP_COMMIT();

    int is64 = g_idx_is64;
    float c1[2][4][4], c2[2][4][4];
    Gath g;

    // ---- prologue: GEMM1(t0) ----
    {
        int nv = min(TILE, n_edges - t0 * TILE);
        pregather(eidx, is64, n_edges, t0, nv, src_embed, rx_embed, g);
        CP_WAIT0();
        __syncthreads();
        float* A = smem + ((t0 & 1) ? SA1 : SA0);
        acc_zero(c1);
        gemm64<true>(A, smem + SW1, c1);
        __syncthreads();                       // reads of A done
        if (t0 + 1 < t1)
            prefetch_tile(eattr, (size_t)(t0 + 1) * TILE,
                          min(TILE, n_edges - (t0 + 1) * TILE),
                          sb + (((t0 + 1) & 1) ? SA1 : SA0) * 4);
        CP_COMMIT();
        epi1(c1, g, A, out_edge, t0, nv);      // agg(t0) -> A-buffer[t0&1]
        CP_WAIT0();
        __syncthreads();                       // agg visible; A(t0+1) loaded
    }

    // ---- main loop: dual[GEMM2(i) | GEMM1(i+1)] ----
    for (int i = t0; i < t1 - 1; i++) {
        float* Aagg  = smem + ((i & 1) ? SA1 : SA0);        // agg(i)
        float* Anext = smem + (((i + 1) & 1) ? SA1 : SA0);  // eattr(i+1)
        int nv_i  = min(TILE, n_edges - i * TILE);
        int nv_n  = min(TILE, n_edges - (i + 1) * TILE);

        pregather(eidx, is64, n_edges, i + 1, nv_n, src_embed, rx_embed, g);

        acc_zero(c1); acc_zero(c2);
        gemm_dual2(Aagg, smem + SW2, c2, Anext, smem + SW1, c1);
        __syncthreads();                       // reads of both A buffers done

        if (i + 2 < t1)
            prefetch_tile(eattr, (size_t)(i + 2) * TILE,
                          min(TILE, n_edges - (i + 2) * TILE),
                          sb + ((i & 1) ? SA1 : SA0) * 4);  // reuse agg(i) buf
        CP_COMMIT();

        epi2(c2, out_upd, i, nv_i);            // upd(i) out
        epi1(c1, g, Anext, out_edge, i + 1, nv_n);  // edge(i+1) out, agg(i+1)

        CP_WAIT0();
        __syncthreads();                       // agg(i+1) visible; A(i+2) loaded
    }

    // ---- tail: GEMM2(t1-1) ----
    {
        int t = t1 - 1;
        float* A = smem + ((t & 1) ? SA1 : SA0);
        int nv = min(TILE, n_edges - t * TILE);
        acc_zero(c2);
        gemm64<false>(A, smem + SW2, c2);
        epi2(c2, out_upd, t, nv);
    }
}

// ---------------------------------------------------------------------------
// Launch: inputs x, edge_index, edge_attr, W_src, W_edge, W_rx, W_agg
// Output: concat(src_embed[N,D], edge_embed[E,D], rx_embed[N,D], updated[E,D])
// ---------------------------------------------------------------------------
extern "C" void kernel_launch(void* const* d_in, const int* in_sizes, int n_in,
                              void* d_out, int out_size) {
    const float* x     = (const float*)d_in[0];
    const void*  eidx  = d_in[1];
    const float* eattr = (const float*)d_in[2];
    const float* Wsrc  = (const float*)d_in[3];
    const float* Wedge = (const float*)d_in[4];
    const float* Wrx   = (const float*)d_in[5];
    const float* Wagg  = (const float*)d_in[6];

    int N = in_sizes[0] / DIMS;
    int E = in_sizes[2] / DIMS;

    float* out      = (float*)d_out;
    float* out_src  = out;
    float* out_edge = out_src + (size_t)N * DIMS;
    float* out_rx   = out_edge + (size_t)E * DIMS;
    float* out_upd  = out_rx + (size_t)N * DIMS;

    int ntiles_n = (N + TILE - 1) / TILE;
    int ntiles_e = (E + TILE - 1) / TILE;
    int tpc_n = (ntiles_n + 147) / 148;          // ~1 wave of CTAs
    int grid_n = (ntiles_n + tpc_n - 1) / tpc_n;
    int tpc_e = (ntiles_e + 4 * 148 - 1) / (4 * 148);  // ~4 waves
    int grid_e = (ntiles_e + tpc_e - 1) / tpc_e;

    size_t smem_bytes = (size_t)SMEM_FLOATS * sizeof(float);  // 202752 B
    cudaFuncSetAttribute(node_kernel, cudaFuncAttributeMaxDynamicSharedMemorySize,
                         (int)smem_bytes);
    cudaFuncSetAttribute(edge_kernel, cudaFuncAttributeMaxDynamicSharedMemorySize,
                         (int)smem_bytes);

    node_kernel<<<grid_n, NTHREADS, smem_bytes>>>(
        x, Wsrc, Wrx, eidx, out_src, out_rx, N, tpc_n, ntiles_n);
    edge_kernel<<<grid_e, NTHREADS, smem_bytes>>>(
        eattr, eidx, Wedge, Wagg, out_src, out_rx, out_edge, out_upd,
        E, tpc_e, ntiles_e);
}

// round 17
// speedup vs baseline: 1.7432x; 1.2946x over previous
#include <cuda_runtime.h>
#include <cuda_fp16.h>
#include <cstdint>

#define DIMS 128
#define TILE 64
#define SROWH 136         // smem row stride in HALVES: (4*row+lane) bank spread
#define NTHREADS 256

// smem layout in halves
#define HA0 0
#define HA1 (TILE * SROWH)                 // 8704
#define HW1 (2 * TILE * SROWH)             // 17408
#define HW2 (HW1 + DIMS * SROWH)           // 34816
#define SMEM_HALVES (HW2 + DIMS * SROWH)   // 52224 halves = 104448 B

__device__ int g_idx_is64;

// ---------------------------------------------------------------------------
// helpers
// ---------------------------------------------------------------------------
__device__ __forceinline__ float2 ldg2_pin(const float* p) {
    float2 v;
    asm volatile("ld.global.nc.v2.f32 {%0,%1}, [%2];"
                 : "=f"(v.x), "=f"(v.y) : "l"(p));
    return v;
}

__device__ __forceinline__ float4 ldg4_pin(const float* p) {
    float4 v;
    asm volatile("ld.global.nc.v4.f32 {%0,%1,%2,%3}, [%4];"
                 : "=f"(v.x), "=f"(v.y), "=f"(v.z), "=f"(v.w) : "l"(p));
    return v;
}

__device__ __forceinline__ uint32_t h2u(__half2 h) {
    return *(uint32_t*)&h;
}

// fp16 mma: D(16x8) += A(16x16) * B(8x16)^T, fp32 accum
__device__ __forceinline__ void mma16(float c[4], const uint32_t a[4],
                                      const uint32_t b[2]) {
    asm volatile(
        "mma.sync.aligned.m16n8k16.row.col.f32.f16.f16.f32 "
        "{%0,%1,%2,%3}, {%4,%5,%6,%7}, {%8,%9}, {%0,%1,%2,%3};"
        : "+f"(c[0]), "+f"(c[1]), "+f"(c[2]), "+f"(c[3])
        : "r"(a[0]), "r"(a[1]), "r"(a[2]), "r"(a[3]), "r"(b[0]), "r"(b[1]));
}

// Weight [128,128] fp32 -> smem fp16 (RN), once per CTA.
__device__ __forceinline__ void load_w(const float* __restrict__ w, __half* s) {
    int tid = threadIdx.x;
    #pragma unroll
    for (int it = 0; it < 16; it++) {
        int idx = tid + it * NTHREADS;
        int row = idx >> 5;
        int c   = idx & 31;
        float4 v = *(const float4*)(w + row * DIMS + 4 * c);
        uint32_t u0 = h2u(__float22half2_rn(make_float2(v.x, v.y)));
        uint32_t u1 = h2u(__float22half2_rn(make_float2(v.z, v.w)));
        *(uint2*)(s + row * SROWH + 4 * c) = make_uint2(u0, u1);
    }
}

// Register-staged tile prefetch: 8x LDG.128 per thread (pinned early).
__device__ __forceinline__ void pf_load(float4 pf[8], const float* __restrict__ g,
                                        size_t row0, int nrows) {
    int tid = threadIdx.x;
    #pragma unroll
    for (int it = 0; it < 8; it++) {
        int idx = tid + it * NTHREADS;
        int row = idx >> 5;
        int c   = idx & 31;
        if (row < nrows) pf[it] = ldg4_pin(g + (row0 + row) * DIMS + 4 * c);
        else             pf[it] = make_float4(0.f, 0.f, 0.f, 0.f);
    }
}

// Convert staged registers to fp16 and store the 64x128 tile.
__device__ __forceinline__ void sts_tile(const float4 pf[8], __half* A) {
    int tid = threadIdx.x;
    #pragma unroll
    for (int it = 0; it < 8; it++) {
        int idx = tid + it * NTHREADS;
        int row = idx >> 5;
        int c   = idx & 31;
        uint32_t u0 = h2u(__float22half2_rn(make_float2(pf[it].x, pf[it].y)));
        uint32_t u1 = h2u(__float22half2_rn(make_float2(pf[it].z, pf[it].w)));
        *(uint2*)(A + row * SROWH + 4 * c) = make_uint2(u0, u1);
    }
}

// ---------------------------------------------------------------------------
// fp16 GEMMs: 8 warps as 2(row) x 4(col), warp tile 32x32.
// Accum c[i][j][4]: row = wr*32+i*16+gid+8h, col = wc*32+j*8+t4*2(+1).
// Per k16-step: A 4 LDS.32/m-tile, B 2 LDS.32/n-tile (banks (4*gid+t4)%32, CF).
// ---------------------------------------------------------------------------
__device__ __forceinline__ void gemm_h(const __half* __restrict__ As,
                                       const __half* __restrict__ Bs,
                                       float c[2][4][4]) {
    int wid = threadIdx.x >> 5, lane = threadIdx.x & 31;
    int wr = wid & 1, wc = wid >> 1;
    int gid = lane >> 2, t4 = lane & 3;
    const __half* Ab = As + (wr * 32 + gid) * SROWH + 2 * t4;
    const __half* Bb = Bs + (wc * 32 + gid) * SROWH + 2 * t4;

    #pragma unroll
    for (int k = 0; k < DIMS; k += 16) {
        uint32_t a[2][4], b[4][2];
        #pragma unroll
        for (int i = 0; i < 2; i++) {
            const __half* p = Ab + i * 16 * SROWH + k;
            a[i][0] = *(const uint32_t*)(p);
            a[i][1] = *(const uint32_t*)(p + 8 * SROWH);
            a[i][2] = *(const uint32_t*)(p + 8);
            a[i][3] = *(const uint32_t*)(p + 8 * SROWH + 8);
        }
        #pragma unroll
        for (int j = 0; j < 4; j++) {
            const __half* p = Bb + j * 8 * SROWH + k;
            b[j][0] = *(const uint32_t*)(p);
            b[j][1] = *(const uint32_t*)(p + 8);
        }
        #pragma unroll
        for (int i = 0; i < 2; i++)
            #pragma unroll
            for (int j = 0; j < 4; j++) mma16(c[i][j], a[i], b[j]);
    }
}

// Cross-tile dual GEMM: c2 += A2@B2^T, c1 += A1@B1^T (16 indep mma/k-step).
__device__ __forceinline__ void gemm_dual_h(const __half* __restrict__ A2s,
                                            const __half* __restrict__ B2s,
                                            float c2[2][4][4],
                                            const __half* __restrict__ A1s,
                                            const __half* __restrict__ B1s,
                                            float c1[2][4][4]) {
    int wid = threadIdx.x >> 5, lane = threadIdx.x & 31;
    int wr = wid & 1, wc = wid >> 1;
    int gid = lane >> 2, t4 = lane & 3;
    const __half* A2b = A2s + (wr * 32 + gid) * SROWH + 2 * t4;
    const __half* A1b = A1s + (wr * 32 + gid) * SROWH + 2 * t4;
    const __half* B2b = B2s + (wc * 32 + gid) * SROWH + 2 * t4;
    const __half* B1b = B1s + (wc * 32 + gid) * SROWH + 2 * t4;

    #pragma unroll
    for (int k = 0; k < DIMS; k += 16) {
        uint32_t a2[2][4], a1[2][4], b2[4][2], b1[4][2];
        #pragma unroll
        for (int i = 0; i < 2; i++) {
            const __half* p = A2b + i * 16 * SROWH + k;
            a2[i][0] = *(const uint32_t*)(p);
            a2[i][1] = *(const uint32_t*)(p + 8 * SROWH);
            a2[i][2] = *(const uint32_t*)(p + 8);
            a2[i][3] = *(const uint32_t*)(p + 8 * SROWH + 8);
            const __half* q = A1b + i * 16 * SROWH + k;
            a1[i][0] = *(const uint32_t*)(q);
            a1[i][1] = *(const uint32_t*)(q + 8 * SROWH);
            a1[i][2] = *(const uint32_t*)(q + 8);
            a1[i][3] = *(const uint32_t*)(q + 8 * SROWH + 8);
        }
        #pragma unroll
        for (int j = 0; j < 4; j++) {
            const __half* p = B2b + j * 8 * SROWH + k;
            b2[j][0] = *(const uint32_t*)(p);
            b2[j][1] = *(const uint32_t*)(p + 8);
            const __half* q = B1b + j * 8 * SROWH + k;
            b1[j][0] = *(const uint32_t*)(q);
            b1[j][1] = *(const uint32_t*)(q + 8);
        }
        #pragma unroll
        for (int i = 0; i < 2; i++)
            #pragma unroll
            for (int j = 0; j < 4; j++) {
                mma16(c2[i][j], a2[i], b2[j]);
                mma16(c1[i][j], a1[i], b1[j]);
            }
    }
}

__device__ __forceinline__ void acc_zero(float c[2][4][4]) {
    #pragma unroll
    for (int i = 0; i < 2; i++)
        #pragma unroll
        for (int j = 0; j < 4; j++)
            #pragma unroll
            for (int q = 0; q < 4; q++) c[i][j][q] = 0.f;
}

// ---------------------------------------------------------------------------
// Node kernel: persistent over tiles; src = x@Wsrc^T, rx = x@Wrx^T
// (one shared-A dual GEMM per tile). Block 0 also detects edge_index dtype.
// ---------------------------------------------------------------------------
extern __shared__ __half smemh[];

__global__ void __launch_bounds__(NTHREADS, 1)
node_kernel(const float* __restrict__ x, const float* __restrict__ Wsrc,
            const float* __restrict__ Wrx, const void* __restrict__ eidx,
            float* __restrict__ out_src, float* __restrict__ out_rx,
            int n_nodes, int tiles_per_cta, int ntiles) {
    if (blockIdx.x == 0 && threadIdx.x == 0) {
        const long long* p = (const long long*)eidx;
        int ok = 1;
        for (int i = 0; i < 32; i++) {
            long long v = p[i];
            if (v < 0 || v >= (long long)n_nodes) ok = 0;
        }
        g_idx_is64 = ok;
    }

    int t0 = blockIdx.x * tiles_per_cta;
    if (t0 >= ntiles) return;
    int t1 = min(t0 + tiles_per_cta, ntiles);

    load_w(Wsrc, smemh + HW1);
    load_w(Wrx,  smemh + HW2);

    float4 pf[8];
    {   // direct load A(t0)
        float4 tmp[8];
        pf_load(tmp, x, (size_t)t0 * TILE, min(TILE, n_nodes - t0 * TILE));
        sts_tile(tmp, smemh + ((t0 & 1) ? HA1 : HA0));
    }
    if (t0 + 1 < t1)
        pf_load(pf, x, (size_t)(t0 + 1) * TILE,
                min(TILE, n_nodes - (t0 + 1) * TILE));
    __syncthreads();

    int wid = threadIdx.x >> 5, lane = threadIdx.x & 31;
    int wr = wid & 1, wc = wid >> 1;
    int gid = lane >> 2, t4 = lane & 3;

    for (int t = t0; t < t1; t++) {
        __half* A = smemh + ((t & 1) ? HA1 : HA0);
        int nvalid = min(TILE, n_nodes - t * TILE);

        float c1[2][4][4], c2[2][4][4];
        acc_zero(c1); acc_zero(c2);
        gemm_dual_h(A, smemh + HW1, c1, A, smemh + HW2, c2);
        __syncthreads();                // reads of A done

        if (t + 1 < t1) sts_tile(pf, smemh + (((t + 1) & 1) ? HA1 : HA0));
        if (t + 2 < t1)
            pf_load(pf, x, (size_t)(t + 2) * TILE,
                    min(TILE, n_nodes - (t + 2) * TILE));

        #pragma unroll
        for (int i = 0; i < 2; i++)
            #pragma unroll
            for (int h = 0; h < 2; h++) {
                int r = wr * 32 + i * 16 + gid + 8 * h;
                if (r < nvalid) {
                    size_t rowoff = ((size_t)t * TILE + r) * DIMS + wc * 32 + t4 * 2;
                    #pragma unroll
                    for (int j = 0; j < 4; j++) {
                        *(float2*)(out_src + rowoff + j * 8) =
                            make_float2(c1[i][j][2 * h], c1[i][j][2 * h + 1]);
                        *(float2*)(out_rx + rowoff + j * 8) =
                            make_float2(c2[i][j][2 * h], c2[i][j][2 * h + 1]);
                    }
                }
            }
        __syncthreads();                // A(t+1) visible before next GEMM
    }
}

// ---------------------------------------------------------------------------
// Edge kernel: cross-tile software pipeline (R16 structure, fp16 tiles).
//   prologue: GEMM1(t0) -> edge out + agg(t0)
//   loop i:   dual[GEMM2(i) | GEMM1(i+1)] -> upd(i), edge(i+1), agg(i+1)
//   tail:     GEMM2(t1-1) -> upd out
// ---------------------------------------------------------------------------
struct Gath { float2 su[4][4], rv[4][4]; };

__device__ __forceinline__ void pregather(const void* eidx, int is64,
                                          int n_edges, int t, int nvalid,
                                          const float* __restrict__ src_embed,
                                          const float* __restrict__ rx_embed,
                                          Gath& g) {
    int wid = threadIdx.x >> 5, lane = threadIdx.x & 31;
    int wr = wid & 1, wc = wid >> 1;
    int gid = lane >> 2, t4 = lane & 3;
    const long long* p64 = (const long long*)eidx;
    const int*       p32 = (const int*)eidx;
    #pragma unroll
    for (int i = 0; i < 2; i++)
        #pragma unroll
        for (int h = 0; h < 2; h++) {
            int r = wr * 32 + i * 16 + gid + 8 * h;
            int ri = i * 2 + h;
            if (r < nvalid) {
                size_t e = (size_t)t * TILE + r;
                long long u, v;
                if (is64) { u = p64[e]; v = p64[(size_t)n_edges + e]; }
                else      { u = p32[e]; v = p32[(size_t)n_edges + e]; }
                const float* sup = src_embed + (size_t)u * DIMS + wc * 32 + t4 * 2;
                const float* rvp = rx_embed  + (size_t)v * DIMS + wc * 32 + t4 * 2;
                #pragma unroll
                for (int j = 0; j < 4; j++) {
                    g.su[ri][j] = ldg2_pin(sup + j * 8);
                    g.rv[ri][j] = ldg2_pin(rvp + j * 8);
                }
            } else {
                #pragma unroll
                for (int j = 0; j < 4; j++) {
                    g.su[ri][j] = make_float2(0.f, 0.f);
                    g.rv[ri][j] = make_float2(0.f, 0.f);
                }
            }
        }
}

// Epilogue GEMM1(t): write edge_embed (fp32), build agg (fp16) into A.
__device__ __forceinline__ void epi1(float c1[2][4][4], const Gath& g,
                                     __half* __restrict__ A,
                                     float* __restrict__ out_edge,
                                     int t, int nvalid) {
    int wid = threadIdx.x >> 5, lane = threadIdx.x & 31;
    int wr = wid & 1, wc = wid >> 1;
    int gid = lane >> 2, t4 = lane & 3;
    #pragma unroll
    for (int i = 0; i < 2; i++)
        #pragma unroll
        for (int h = 0; h < 2; h++) {
            int r = wr * 32 + i * 16 + gid + 8 * h;
            int ri = i * 2 + h;
            if (r < nvalid) {
                size_t e = (size_t)t * TILE + r;
                int colb = wc * 32 + t4 * 2;
                float* ge = out_edge + e * DIMS + colb;
                __half* sa = A + r * SROWH + colb;
                #pragma unroll
                for (int j = 0; j < 4; j++) {
                    float2 a = make_float2(c1[i][j][2 * h], c1[i][j][2 * h + 1]);
                    *(float2*)(ge + j * 8) = a;                 // edge_embed out
                    a.x += g.su[ri][j].x + g.rv[ri][j].x;
                    a.y += g.su[ri][j].y + g.rv[ri][j].y;
                    *(uint32_t*)(sa + j * 8) = h2u(__float22half2_rn(a));
                }
            }
        }
}

__device__ __forceinline__ void epi2(float c2[2][4][4],
                                     float* __restrict__ out_upd,
                                     int t, int nvalid) {
    int wid = threadIdx.x >> 5, lane = threadIdx.x & 31;
    int wr = wid & 1, wc = wid >> 1;
    int gid = lane >> 2, t4 = lane & 3;
    #pragma unroll
    for (int i = 0; i < 2; i++)
        #pragma unroll
        for (int h = 0; h < 2; h++) {
            int r = wr * 32 + i * 16 + gid + 8 * h;
            if (r < nvalid) {
                float* go = out_upd + ((size_t)t * TILE + r) * DIMS
                          + wc * 32 + t4 * 2;
                #pragma unroll
                for (int j = 0; j < 4; j++)
                    *(float2*)(go + j * 8) =
                        make_float2(c2[i][j][2 * h], c2[i][j][2 * h + 1]);
            }
        }
}

__global__ void __launch_bounds__(NTHREADS, 1)
edge_kernel(const float* __restrict__ eattr, const void* __restrict__ eidx,
            const float* __restrict__ Wedge, const float* __restrict__ Wagg,
            const float* __restrict__ src_embed, const float* __restrict__ rx_embed,
            float* __restrict__ out_edge, float* __restrict__ out_upd,
            int n_edges, int tiles_per_cta, int ntiles) {
    int t0 = blockIdx.x * tiles_per_cta;
    if (t0 >= ntiles) return;
    int t1 = min(t0 + tiles_per_cta, ntiles);

    load_w(Wedge, smemh + HW1);
    load_w(Wagg,  smemh + HW2);

    int is64 = g_idx_is64;
    float c1[2][4][4], c2[2][4][4];
    Gath g;
    float4 pf[8];

    // ---- prologue: GEMM1(t0) ----
    {
        int nv = min(TILE, n_edges - t0 * TILE);
        {
            float4 tmp[8];
            pf_load(tmp, eattr, (size_t)t0 * TILE, nv);
            sts_tile(tmp, smemh + ((t0 & 1) ? HA1 : HA0));
        }
        if (t0 + 1 < t1)
            pf_load(pf, eattr, (size_t)(t0 + 1) * TILE,
                    min(TILE, n_edges - (t0 + 1) * TILE));
        __syncthreads();

        pregather(eidx, is64, n_edges, t0, nv, src_embed, rx_embed, g);
        __half* A = smemh + ((t0 & 1) ? HA1 : HA0);
        acc_zero(c1);
        gemm_h(A, smemh + HW1, c1);
        __syncthreads();                       // reads of A done

        if (t0 + 1 < t1) sts_tile(pf, smemh + (((t0 + 1) & 1) ? HA1 : HA0));
        if (t0 + 2 < t1)
            pf_load(pf, eattr, (size_t)(t0 + 2) * TILE,
                    min(TILE, n_edges - (t0 + 2) * TILE));
        epi1(c1, g, A, out_edge, t0, nv);      // agg(t0)
        __syncthreads();
    }

    // ---- main loop: invariant at top: A(i+1)+agg(i) in smem, pf = A(i+2) ----
    for (int i = t0; i < t1 - 1; i++) {
        __half* Aagg  = smemh + ((i & 1) ? HA1 : HA0);
        __half* Anext = smemh + (((i + 1) & 1) ? HA1 : HA0);
        int nv_i = min(TILE, n_edges - i * TILE);
        int nv_n = min(TILE, n_edges - (i + 1) * TILE);

        pregather(eidx, is64, n_edges, i + 1, nv_n, src_embed, rx_embed, g);

        acc_zero(c1); acc_zero(c2);
        gemm_dual_h(Aagg, smemh + HW2, c2, Anext, smemh + HW1, c1);
        __syncthreads();                       // reads of both A buffers done

        if (i + 2 < t1) sts_tile(pf, smemh + ((i & 1) ? HA1 : HA0)); // A(i+2)
        if (i + 3 < t1)
            pf_load(pf, eattr, (size_t)(i + 3) * TILE,
                    min(TILE, n_edges - (i + 3) * TILE));

        epi2(c2, out_upd, i, nv_i);
        epi1(c1, g, Anext, out_edge, i + 1, nv_n);   // agg(i+1)
        __syncthreads();
    }

    // ---- tail: GEMM2(t1-1) ----
    {
        int t = t1 - 1;
        __half* A = smemh + ((t & 1) ? HA1 : HA0);
        int nv = min(TILE, n_edges - t * TILE);
        acc_zero(c2);
        gemm_h(A, smemh + HW2, c2);
        epi2(c2, out_upd, t, nv);
    }
}

// ---------------------------------------------------------------------------
// Launch: inputs x, edge_index, edge_attr, W_src, W_edge, W_rx, W_agg
// Output: concat(src_embed[N,D], edge_embed[E,D], rx_embed[N,D], updated[E,D])
// ---------------------------------------------------------------------------
extern "C" void kernel_launch(void* const* d_in, const int* in_sizes, int n_in,
                              void* d_out, int out_size) {
    const float* x     = (const float*)d_in[0];
    const void*  eidx  = d_in[1];
    const float* eattr = (const float*)d_in[2];
    const float* Wsrc  = (const float*)d_in[3];
    const float* Wedge = (const float*)d_in[4];
    const float* Wrx   = (const float*)d_in[5];
    const float* Wagg  = (const float*)d_in[6];

    int N = in_sizes[0] / DIMS;
    int E = in_sizes[2] / DIMS;

    float* out      = (float*)d_out;
    float* out_src  = out;
    float* out_edge = out_src + (size_t)N * DIMS;
    float* out_rx   = out_edge + (size_t)E * DIMS;
    float* out_upd  = out_rx + (size_t)N * DIMS;

    int ntiles_n = (N + TILE - 1) / TILE;
    int ntiles_e = (E + TILE - 1) / TILE;
    int tpc_n = (ntiles_n + 147) / 148;
    int grid_n = (ntiles_n + tpc_n - 1) / tpc_n;
    int tpc_e = (ntiles_e + 4 * 148 - 1) / (4 * 148);
    int grid_e = (ntiles_e + tpc_e - 1) / tpc_e;

    size_t smem_bytes = (size_t)SMEM_HALVES * sizeof(__half);  // 104448 B
    cudaFuncSetAttribute(node_kernel, cudaFuncAttributeMaxDynamicSharedMemorySize,
                         (int)smem_bytes);
    cudaFuncSetAttribute(edge_kernel, cudaFuncAttributeMaxDynamicSharedMemorySize,
                         (int)smem_bytes);

    node_kernel<<<grid_n, NTHREADS, smem_bytes>>>(
        x, Wsrc, Wrx, eidx, out_src, out_rx, N, tpc_n, ntiles_n);
    edge_kernel<<<grid_e, NTHREADS, smem_bytes>>>(
        eattr, eidx, Wedge, Wagg, out_src, out_rx, out_edge, out_upd,
        E, tpc_e, ntiles_e);
}